// round 4
// baseline (speedup 1.0000x reference)
#include <cuda_runtime.h>
#include <cuda_bf16.h>

#define N_NODES 50000
#define N_EDGES 800000

// ---------------- scratch (static device globals; no allocation) ----------------
static __device__ float  g_agg[(size_t)N_NODES * 128];
static __device__ float  g_deg[N_NODES];
static __device__ float  g_y1 [(size_t)N_NODES * 256];
static __device__ float  g_t1 [(size_t)N_NODES * 512];
static __device__ float  g_h2 [(size_t)N_NODES * 256];
static __device__ float  g_p  [(size_t)N_NODES * 128];
static __device__ float  g_r2 [(size_t)N_NODES * 128];
static __device__ float  g_y2 [(size_t)N_NODES * 128];
static __device__ float  g_t3 [(size_t)N_NODES * 256];
static __device__ double g_sums[4];
static __device__ float  g_stats[4];   // mu1, rsigma1, mu2, rsigma2
static __device__ int    g_is64;

// ---------------- init ----------------
__global__ void k_init(const unsigned long long* __restrict__ ei)
{
    int ok = 1;
#pragma unroll
    for (int i = 0; i < 16; i++)
        ok &= ((ei[i] >> 32) == 0ull) ? 1 : 0;
    g_is64 = ok;
    g_sums[0] = 0.0; g_sums[1] = 0.0; g_sums[2] = 0.0; g_sums[3] = 0.0;
}

__global__ void k_zerof(float* __restrict__ p, int n)
{
    int i = blockIdx.x * blockDim.x + threadIdx.x;
    if (i < n) p[i] = 0.0f;
}

// ---------------- edge scatter: warp per edge, float4 vector-RED per lane ----------------
__global__ void k_scatter(const void* __restrict__ ei, const float* __restrict__ feat,
                          float* __restrict__ agg, float* __restrict__ deg, int addDeg)
{
    int gw   = (blockIdx.x * blockDim.x + threadIdx.x) >> 5;
    int lane = threadIdx.x & 31;
    if (gw >= N_EDGES) return;

    long long s, d;
    if (g_is64) {
        const long long* p = (const long long*)ei;
        s = p[gw]; d = p[N_EDGES + gw];
    } else {
        const int* p = (const int*)ei;
        s = p[gw];  d = p[N_EDGES + gw];
    }

    float4 v = reinterpret_cast<const float4*>(feat + s * 128)[lane];
    float* dp = agg + d * 128 + lane * 4;
    asm volatile("red.global.add.v4.f32 [%0], {%1,%2,%3,%4};"
                 :: "l"(dp), "f"(v.x), "f"(v.y), "f"(v.z), "f"(v.w) : "memory");
    if (addDeg && lane == 0) atomicAdd(deg + d, 1.0f);
}

// ---------------- single-pass TF32 tensor-core GEMM, 2-stage pipelined ----------------
// C = A@B (+bias)(+relu)(+global stats), fp32 in/out, tf32 mma.m16n8k8.
// Tile 128x128, k-step 32, 256 threads = 8 warps (2m x 4n), warp tile 64x32.
// Ping-pong smem (dynamic, 72KB): LOAD(k+1) -> MMA(k) -> CVT+STS(k+1) -> 1 sync.
// AMODE 0: plain A[M,K]
// AMODE 1: conv1 dual-A (k<128: agg*inv_deg; else x), dual-B (Wl/Wr), K=256 virtual
// AMODE 2: A' = relu((A - mu) * rsigma * lnw[k] + lnb[k])
#define ASTR 36                       // row stride in u32; ldmatrix conflict-free
#define TILE_U32 (128 * ASTR)         // one tile (A or B)
#define STAGE_U32 (2 * TILE_U32)      // A + B per stage
#define GEMM_SMEM_BYTES (2 * STAGE_U32 * 4)

__device__ __forceinline__ unsigned f2tf32(float v)
{
    unsigned u;
    asm("cvt.rna.tf32.f32 %0, %1;" : "=r"(u) : "f"(v));
    return u;
}

__device__ __forceinline__ void ldsm4(unsigned* r, unsigned addr)
{
    asm volatile("ldmatrix.sync.aligned.m8n8.x4.shared.b16 {%0,%1,%2,%3}, [%4];"
                 : "=r"(r[0]), "=r"(r[1]), "=r"(r[2]), "=r"(r[3]) : "r"(addr));
}

__device__ __forceinline__ void mma_tf32(float* c, const unsigned* a, const unsigned* b)
{
    asm volatile(
        "mma.sync.aligned.m16n8k8.row.col.f32.tf32.tf32.f32 "
        "{%0,%1,%2,%3}, {%4,%5,%6,%7}, {%8,%9}, {%0,%1,%2,%3};\n"
        : "+f"(c[0]), "+f"(c[1]), "+f"(c[2]), "+f"(c[3])
        : "r"(a[0]), "r"(a[1]), "r"(a[2]), "r"(a[3]), "r"(b[0]), "r"(b[1]));
}

template <int AMODE, bool RELU, bool BIAS, bool STATS>
__global__ void __launch_bounds__(256, 1)
k_gemm(const float* __restrict__ A, const float* __restrict__ A2,
       const float* __restrict__ B, const float* __restrict__ B2,
       const float* __restrict__ bias, float* __restrict__ C,
       int M, int Nc, int K,
       const float* __restrict__ deg,
       const float* __restrict__ lnw, const float* __restrict__ lnb,
       const float* __restrict__ stats, double* __restrict__ sums)
{
    extern __shared__ __align__(16) unsigned dsm[];
    __shared__ double sred[256];

    const int tid  = threadIdx.x;
    const int lane = tid & 31;
    const int wid  = tid >> 5;
    const int g    = lane >> 2;
    const int t4   = lane & 3;
    const int warpM = (wid >> 2) * 64;
    const int warpN = (wid & 3) * 32;
    const int rowBase = blockIdx.y * 128;
    const int colBase = blockIdx.x * 128;

    float mu = 0.f, rs = 0.f;
    if (AMODE == 2) { mu = stats[0]; rs = stats[1]; }

    float acc[4][4][4];
#pragma unroll
    for (int i = 0; i < 4; i++)
#pragma unroll
        for (int j = 0; j < 4; j++)
#pragma unroll
            for (int k = 0; k < 4; k++) acc[i][j][k] = 0.f;

    // fill mappings
    const int aR = tid >> 2;            // A row (and +64)
    const int aK = (tid & 3) * 8;       // A k base (+ cc*4)
    const int bK0 = (tid & 7) * 4;      // B k base
    const int bN0 = (tid >> 3) * 4;     // B n base

    // ldmatrix lane base addresses (stage 0)
    const unsigned smBase = (unsigned)__cvta_generic_to_shared(dsm);
    const unsigned aBase0 = smBase + (((warpM + (lane & 7) + ((lane >> 3) & 1) * 8) * ASTR)
                                      + ((lane >> 4) & 1) * 4) * 4u;
    const unsigned bBase0 = smBase + (TILE_U32 + ((warpN + (lane & 7)) * ASTR) + (lane >> 3) * 4) * 4u;

    // -------- staging registers --------
    float4 aReg[2][2];
    float  degReg[2];
    float4 bReg[4];

    auto LOAD = [&](int k0) {
#pragma unroll
        for (int rr = 0; rr < 2; rr++) {
            int grow = rowBase + aR + rr * 64;
            bool ok = grow < M;
            if (AMODE == 1 && k0 < 128) degReg[rr] = ok ? deg[grow] : 1.0f;
#pragma unroll
            for (int cc = 0; cc < 2; cc++) {
                int k = k0 + aK + cc * 4;
                float4 v = make_float4(0.f, 0.f, 0.f, 0.f);
                if (ok) {
                    if (AMODE == 1) {
                        v = (k < 128)
                          ? *reinterpret_cast<const float4*>(A  + (size_t)grow * 128 + k)
                          : *reinterpret_cast<const float4*>(A2 + (size_t)grow * 128 + (k - 128));
                    } else {
                        v = *reinterpret_cast<const float4*>(A + (size_t)grow * K + k);
                    }
                }
                aReg[rr][cc] = v;
            }
        }
#pragma unroll
        for (int i = 0; i < 4; i++) {
            int kg = k0 + bK0 + i;
            const float* Bp = B;
            int kk = kg;
            if (AMODE == 1 && kg >= 128) { Bp = B2; kk = kg - 128; }
            bReg[i] = *reinterpret_cast<const float4*>(Bp + (size_t)kk * Nc + colBase + bN0);
        }
    };

    auto STORE = [&](int stage, int k0) {
        unsigned* Asp = dsm + stage * STAGE_U32;
        unsigned* Bsp = Asp + TILE_U32;
#pragma unroll
        for (int rr = 0; rr < 2; rr++) {
            int r = aR + rr * 64;
            float inv = 1.0f;
            if (AMODE == 1 && k0 < 128) inv = 1.0f / fmaxf(degReg[rr], 1.0f);
#pragma unroll
            for (int cc = 0; cc < 2; cc++) {
                int c = aK + cc * 4;
                float4 v = aReg[rr][cc];
                if (AMODE == 1 && k0 < 128) {
                    v.x *= inv; v.y *= inv; v.z *= inv; v.w *= inv;
                }
                if (AMODE == 2) {
                    int k = k0 + c;
                    float4 w4 = *reinterpret_cast<const float4*>(lnw + k);
                    float4 b4 = *reinterpret_cast<const float4*>(lnb + k);
                    v.x = fmaxf((v.x - mu) * rs * w4.x + b4.x, 0.f);
                    v.y = fmaxf((v.y - mu) * rs * w4.y + b4.y, 0.f);
                    v.z = fmaxf((v.z - mu) * rs * w4.z + b4.z, 0.f);
                    v.w = fmaxf((v.w - mu) * rs * w4.w + b4.w, 0.f);
                }
                uint4 t;
                t.x = f2tf32(v.x); t.y = f2tf32(v.y); t.z = f2tf32(v.z); t.w = f2tf32(v.w);
                *reinterpret_cast<uint4*>(&Asp[r * ASTR + c]) = t;
            }
        }
        const float* rf = reinterpret_cast<const float*>(bReg);
#pragma unroll
        for (int j = 0; j < 4; j++) {
            uint4 t;
            t.x = f2tf32(rf[0 * 4 + j]);
            t.y = f2tf32(rf[1 * 4 + j]);
            t.z = f2tf32(rf[2 * 4 + j]);
            t.w = f2tf32(rf[3 * 4 + j]);
            *reinterpret_cast<uint4*>(&Bsp[(bN0 + j) * ASTR + bK0]) = t;
        }
    };

    auto MMA = [&](int stage) {
        unsigned aB = aBase0 + (unsigned)(stage * STAGE_U32 * 4);
        unsigned bB = bBase0 + (unsigned)(stage * STAGE_U32 * 4);
#pragma unroll
        for (int kbp = 0; kbp < 2; kbp++) {
            unsigned bf[4][4];
#pragma unroll
            for (int nt = 0; nt < 4; nt++)
                ldsm4(bf[nt], bB + (unsigned)((nt * 8 * ASTR + kbp * 16) * 4));
#pragma unroll
            for (int kk = 0; kk < 2; kk++) {
                int kb = kbp * 2 + kk;
                unsigned af[4][4];
#pragma unroll
                for (int mt = 0; mt < 4; mt++)
                    ldsm4(af[mt], aB + (unsigned)((mt * 16 * ASTR + kb * 8) * 4));
#pragma unroll
                for (int nt = 0; nt < 4; nt++)
#pragma unroll
                    for (int mt = 0; mt < 4; mt++)
                        mma_tf32(acc[mt][nt], af[mt], &bf[nt][kk * 2]);
            }
        }
    };

    // -------- pipelined mainloop --------
    LOAD(0);
    STORE(0, 0);
    __syncthreads();
    int stage = 0;
    for (int k0 = 32; k0 < K; k0 += 32) {
        LOAD(k0);
        MMA(stage);
        STORE(stage ^ 1, k0);
        __syncthreads();
        stage ^= 1;
    }
    MMA(stage);

    // ---- epilogue ----
    double s1 = 0.0, s2 = 0.0;
#pragma unroll
    for (int nt = 0; nt < 4; nt++) {
        int col = colBase + warpN + nt * 8 + 2 * t4;
        float2 bv = make_float2(0.f, 0.f);
        if (BIAS) bv = *reinterpret_cast<const float2*>(bias + col);
#pragma unroll
        for (int mt = 0; mt < 4; mt++) {
            int r0 = rowBase + warpM + mt * 16 + g;
            float c0 = acc[mt][nt][0] + bv.x;
            float c1 = acc[mt][nt][1] + bv.y;
            float c2 = acc[mt][nt][2] + bv.x;
            float c3 = acc[mt][nt][3] + bv.y;
            if (RELU) {
                c0 = fmaxf(c0, 0.f); c1 = fmaxf(c1, 0.f);
                c2 = fmaxf(c2, 0.f); c3 = fmaxf(c3, 0.f);
            }
            if (r0 < M) {
                *reinterpret_cast<float2*>(C + (size_t)r0 * Nc + col) = make_float2(c0, c1);
                if (STATS) { s1 += (double)c0 + (double)c1;
                             s2 += (double)c0 * c0 + (double)c1 * c1; }
            }
            if (r0 + 8 < M) {
                *reinterpret_cast<float2*>(C + (size_t)(r0 + 8) * Nc + col) = make_float2(c2, c3);
                if (STATS) { s1 += (double)c2 + (double)c3;
                             s2 += (double)c2 * c2 + (double)c3 * c3; }
            }
        }
    }

    if (STATS) {
        sred[tid] = s1; __syncthreads();
        for (int o = 128; o > 0; o >>= 1) { if (tid < o) sred[tid] += sred[tid + o]; __syncthreads(); }
        if (tid == 0) atomicAdd(&sums[0], sred[0]);
        __syncthreads();
        sred[tid] = s2; __syncthreads();
        for (int o = 128; o > 0; o >>= 1) { if (tid < o) sred[tid] += sred[tid + o]; __syncthreads(); }
        if (tid == 0) atomicAdd(&sums[1], sred[0]);
    }
}

// ---------------- conv2 combine: y2 = agg/deg + bl2 + r2, with global stats ----------------
__global__ void k_y2(const float* __restrict__ agg, const float* __restrict__ r2,
                     const float* __restrict__ bl2, const float* __restrict__ deg,
                     float* __restrict__ y2)
{
    __shared__ double sred[256];
    double s1 = 0.0, s2 = 0.0;
    const int n = N_NODES * 128;
    for (int idx = blockIdx.x * blockDim.x + threadIdx.x; idx < n; idx += gridDim.x * blockDim.x) {
        int i = idx >> 7, c = idx & 127;
        float y = agg[idx] / fmaxf(deg[i], 1.0f) + bl2[c] + r2[idx];
        y2[idx] = y;
        s1 += (double)y; s2 += (double)y * (double)y;
    }
    int tid = threadIdx.x;
    sred[tid] = s1; __syncthreads();
    for (int o = 128; o > 0; o >>= 1) { if (tid < o) sred[tid] += sred[tid + o]; __syncthreads(); }
    if (tid == 0) atomicAdd(&g_sums[2], sred[0]);
    __syncthreads();
    sred[tid] = s2; __syncthreads();
    for (int o = 128; o > 0; o >>= 1) { if (tid < o) sred[tid] += sred[tid + o]; __syncthreads(); }
    if (tid == 0) atomicAdd(&g_sums[3], sred[0]);
}

__global__ void k_finalize(int stage)
{
    double cnt = (stage == 0) ? (double)N_NODES * 256.0 : (double)N_NODES * 128.0;
    int o = stage * 2;
    double mu  = g_sums[o] / cnt;
    double var = g_sums[o + 1] / cnt - mu * mu;
    g_stats[o]     = (float)mu;
    g_stats[o + 1] = (float)(1.0 / sqrt(var + 1e-5));
}

// ---------------- launch ----------------
extern "C" void kernel_launch(void* const* d_in, const int* in_sizes, int n_in,
                              void* d_out, int out_size)
{
    const float* x    = (const float*)d_in[0];
    const void*  ei   =               d_in[1];
    const float* Wl1  = (const float*)d_in[2];
    const float* bl1  = (const float*)d_in[3];
    const float* Wr1  = (const float*)d_in[4];
    const float* ln1w = (const float*)d_in[5];
    const float* ln1b = (const float*)d_in[6];
    const float* W1   = (const float*)d_in[7];
    const float* b1   = (const float*)d_in[8];
    const float* W2   = (const float*)d_in[9];
    const float* b2   = (const float*)d_in[10];
    const float* Wl2  = (const float*)d_in[11];
    const float* bl2  = (const float*)d_in[12];
    const float* Wr2  = (const float*)d_in[13];
    const float* ln2w = (const float*)d_in[14];
    const float* ln2b = (const float*)d_in[15];
    const float* W3   = (const float*)d_in[16];
    const float* b3   = (const float*)d_in[17];
    const float* W4   = (const float*)d_in[18];
    const float* b4   = (const float*)d_in[19];
    float* out = (float*)d_out;

    float *agg, *deg, *y1, *t1, *h2, *p, *r2, *y2, *t3, *stats;
    double* sums;
    cudaGetSymbolAddress((void**)&agg,  g_agg);
    cudaGetSymbolAddress((void**)&deg,  g_deg);
    cudaGetSymbolAddress((void**)&y1,   g_y1);
    cudaGetSymbolAddress((void**)&t1,   g_t1);
    cudaGetSymbolAddress((void**)&h2,   g_h2);
    cudaGetSymbolAddress((void**)&p,    g_p);
    cudaGetSymbolAddress((void**)&r2,   g_r2);
    cudaGetSymbolAddress((void**)&y2,   g_y2);
    cudaGetSymbolAddress((void**)&t3,   g_t3);
    cudaGetSymbolAddress((void**)&sums, g_sums);
    cudaGetSymbolAddress((void**)&stats, g_stats);

    // opt-in to >48KB dynamic smem for each template instantiation
    static int smemSet = 0;
    if (!smemSet) {
        cudaFuncSetAttribute(k_gemm<1, false, true,  true >, cudaFuncAttributeMaxDynamicSharedMemorySize, GEMM_SMEM_BYTES);
        cudaFuncSetAttribute(k_gemm<2, true,  true,  false>, cudaFuncAttributeMaxDynamicSharedMemorySize, GEMM_SMEM_BYTES);
        cudaFuncSetAttribute(k_gemm<0, true,  true,  false>, cudaFuncAttributeMaxDynamicSharedMemorySize, GEMM_SMEM_BYTES);
        cudaFuncSetAttribute(k_gemm<0, false, false, false>, cudaFuncAttributeMaxDynamicSharedMemorySize, GEMM_SMEM_BYTES);
        cudaFuncSetAttribute(k_gemm<0, false, true,  false>, cudaFuncAttributeMaxDynamicSharedMemorySize, GEMM_SMEM_BYTES);
        smemSet = 1;
    }

    const int M = N_NODES;
    const unsigned gy = (M + 127) / 128;
    dim3 g1(2, gy), g2(4, gy), g3(2, gy), g4(1, gy);
    const int scatterBlocks = (N_EDGES * 32 + 255) / 256;

    // --- conv1 ---
    k_init<<<1, 1>>>((const unsigned long long*)ei);
    k_zerof<<<(N_NODES * 128 + 255) / 256, 256>>>(agg, N_NODES * 128);
    k_zerof<<<(N_NODES + 255) / 256, 256>>>(deg, N_NODES);
    k_scatter<<<scatterBlocks, 256>>>(ei, x, agg, deg, 1);
    // y1 = (agg/deg)@Wl1 + bl1 + x@Wr1, + global stats for LN1
    k_gemm<1, false, true, true><<<g1, 256, GEMM_SMEM_BYTES>>>(agg, x, Wl1, Wr1, bl1, y1,
                                              M, 256, 256, deg, nullptr, nullptr, nullptr, sums);
    k_finalize<<<1, 1>>>(0);
    // t1 = relu(LN1(y1) @ W1 + b1)
    k_gemm<2, true, true, false><<<g2, 256, GEMM_SMEM_BYTES>>>(y1, nullptr, W1, nullptr, b1, t1,
                                              M, 512, 256, nullptr, ln1w, ln1b, stats + 0, nullptr);
    // h2 = relu(t1 @ W2 + b2)
    k_gemm<0, true, true, false><<<g3, 256, GEMM_SMEM_BYTES>>>(t1, nullptr, W2, nullptr, b2, h2,
                                              M, 256, 512, nullptr, nullptr, nullptr, nullptr, nullptr);

    // --- conv2 (projected-first aggregation: agg(h)@Wl2 == agg(h@Wl2)) ---
    k_gemm<0, false, false, false><<<g4, 256, GEMM_SMEM_BYTES>>>(h2, nullptr, Wl2, nullptr, nullptr, p,
                                                M, 128, 256, nullptr, nullptr, nullptr, nullptr, nullptr);
    k_gemm<0, false, false, false><<<g4, 256, GEMM_SMEM_BYTES>>>(h2, nullptr, Wr2, nullptr, nullptr, r2,
                                                M, 128, 256, nullptr, nullptr, nullptr, nullptr, nullptr);
    k_zerof<<<(N_NODES * 128 + 255) / 256, 256>>>(agg, N_NODES * 128);
    k_scatter<<<scatterBlocks, 256>>>(ei, p, agg, deg, 0);
    k_y2<<<1024, 256>>>(agg, r2, bl2, deg, y2);
    k_finalize<<<1, 1>>>(1);
    // t3 = relu(LN2(y2) @ W3 + b3)
    k_gemm<2, true, true, false><<<g3, 256, GEMM_SMEM_BYTES>>>(y2, nullptr, W3, nullptr, b3, t3,
                                              M, 256, 128, nullptr, ln2w, ln2b, stats + 2, nullptr);
    // out = t3 @ W4 + b4
    k_gemm<0, false, true, false><<<g4, 256, GEMM_SMEM_BYTES>>>(t3, nullptr, W4, nullptr, b4, out,
                                               M, 128, 256, nullptr, nullptr, nullptr, nullptr, nullptr);
}

// round 5
// speedup vs baseline: 1.1396x; 1.1396x over previous
#include <cuda_runtime.h>

#define N_NODES 50000
#define N_EDGES 800000

// ---------------- scratch (static device globals; no allocation) ----------------
static __device__ float    g_agg[(size_t)N_NODES * 128];
static __device__ float    g_deg[N_NODES];
static __device__ unsigned g_a1 [(size_t)N_NODES * 256];   // tf32: [agg/deg | x]
static __device__ float    g_y1 [(size_t)N_NODES * 256];
static __device__ unsigned g_z1 [(size_t)N_NODES * 256];   // tf32 relu(LN1(y1))
static __device__ unsigned g_t1 [(size_t)N_NODES * 512];   // tf32
static __device__ unsigned g_h2 [(size_t)N_NODES * 256];   // tf32
static __device__ float    g_pr [(size_t)N_NODES * 256];   // [p | r2] fp32
static __device__ float    g_y2 [(size_t)N_NODES * 128];
static __device__ unsigned g_z2 [(size_t)N_NODES * 128];   // tf32 relu(LN2(y2))
static __device__ unsigned g_t3 [(size_t)N_NODES * 256];   // tf32
// transposed tf32 weights [n][k]
static __device__ unsigned g_bt1 [256 * 256];
static __device__ unsigned g_w1t [512 * 256];
static __device__ unsigned g_w2t [256 * 512];
static __device__ unsigned g_blr2[256 * 256];
static __device__ unsigned g_w3t [256 * 128];
static __device__ unsigned g_w4t [128 * 256];
static __device__ double   g_sums[4];
static __device__ float    g_stats[4];   // mu1, rsigma1, mu2, rsigma2
static __device__ int      g_is64;

__device__ __forceinline__ unsigned f2tf32(float v)
{
    unsigned u;
    asm("cvt.rna.tf32.f32 %0, %1;" : "=r"(u) : "f"(v));
    return u;
}

// ---------------- init ----------------
__global__ void k_init(const unsigned long long* __restrict__ ei)
{
    int ok = 1;
#pragma unroll
    for (int i = 0; i < 16; i++)
        ok &= ((ei[i] >> 32) == 0ull) ? 1 : 0;
    g_is64 = ok;
    g_sums[0] = 0.0; g_sums[1] = 0.0; g_sums[2] = 0.0; g_sums[3] = 0.0;
}

__global__ void k_zerof(float* __restrict__ p, int n)
{
    int i = blockIdx.x * blockDim.x + threadIdx.x;
    if (i < n) p[i] = 0.0f;
}

// ---------------- weight transpose + tf32 convert: dst[n*stride + k] = tf32(src[k*N + n]) ----------------
__global__ void k_wt(const float* __restrict__ src, unsigned* __restrict__ dst,
                     int K, int N, int stride)
{
    int idx = blockIdx.x * blockDim.x + threadIdx.x;
    if (idx >= K * N) return;
    int k = idx / N, n = idx % N;
    dst[n * stride + k] = f2tf32(src[idx]);
}

// ---------------- edge scatter: warp per edge, float4 vector-RED per lane ----------------
__global__ void k_scatter(const void* __restrict__ ei, const float* __restrict__ feat,
                          int fstride, float* __restrict__ agg, float* __restrict__ deg,
                          int addDeg)
{
    int gw   = (blockIdx.x * blockDim.x + threadIdx.x) >> 5;
    int lane = threadIdx.x & 31;
    if (gw >= N_EDGES) return;

    long long s, d;
    if (g_is64) {
        const long long* p = (const long long*)ei;
        s = p[gw]; d = p[N_EDGES + gw];
    } else {
        const int* p = (const int*)ei;
        s = p[gw];  d = p[N_EDGES + gw];
    }

    float4 v = *reinterpret_cast<const float4*>(feat + (size_t)s * fstride + lane * 4);
    float* dp = agg + (size_t)d * 128 + lane * 4;
    asm volatile("red.global.add.v4.f32 [%0], {%1,%2,%3,%4};"
                 :: "l"(dp), "f"(v.x), "f"(v.y), "f"(v.z), "f"(v.w) : "memory");
    if (addDeg && lane == 0) atomicAdd(deg + d, 1.0f);
}

// ---------------- conv1 A prep: A1 = tf32([agg/deg | x]) ----------------
__global__ void k_prep1(const float* __restrict__ agg, const float* __restrict__ x,
                        const float* __restrict__ deg, unsigned* __restrict__ A1)
{
    int idx = blockIdx.x * blockDim.x + threadIdx.x;   // N*32 threads, 4 cols each
    if (idx >= N_NODES * 32) return;
    int i = idx >> 5, c = (idx & 31) * 4;
    float inv = 1.0f / fmaxf(deg[i], 1.0f);
    float4 a = *reinterpret_cast<const float4*>(agg + (size_t)i * 128 + c);
    float4 xv = *reinterpret_cast<const float4*>(x + (size_t)i * 128 + c);
    uint4 ta, tx;
    ta.x = f2tf32(a.x * inv); ta.y = f2tf32(a.y * inv);
    ta.z = f2tf32(a.z * inv); ta.w = f2tf32(a.w * inv);
    tx.x = f2tf32(xv.x); tx.y = f2tf32(xv.y); tx.z = f2tf32(xv.z); tx.w = f2tf32(xv.w);
    *reinterpret_cast<uint4*>(A1 + (size_t)i * 256 + c) = ta;
    *reinterpret_cast<uint4*>(A1 + (size_t)i * 256 + 128 + c) = tx;
}

// ---------------- LN+ReLU -> tf32 ----------------
__global__ void k_lnrelu(const float* __restrict__ src, unsigned* __restrict__ dst,
                         const float* __restrict__ w, const float* __restrict__ b,
                         int Cmask, int statOff, int total4)
{
    int idx = blockIdx.x * blockDim.x + threadIdx.x;
    if (idx >= total4) return;
    float mu = g_stats[statOff], rs = g_stats[statOff + 1];
    int c = (idx * 4) & Cmask;
    float4 v = reinterpret_cast<const float4*>(src)[idx];
    float4 w4 = *reinterpret_cast<const float4*>(w + c);
    float4 b4 = *reinterpret_cast<const float4*>(b + c);
    uint4 o;
    o.x = f2tf32(fmaxf((v.x - mu) * rs * w4.x + b4.x, 0.f));
    o.y = f2tf32(fmaxf((v.y - mu) * rs * w4.y + b4.y, 0.f));
    o.z = f2tf32(fmaxf((v.z - mu) * rs * w4.z + b4.z, 0.f));
    o.w = f2tf32(fmaxf((v.w - mu) * rs * w4.w + b4.w, 0.f));
    reinterpret_cast<uint4*>(dst)[idx] = o;
}

// ---------------- TF32 tensor-core GEMM, cp.async 2-stage ping-pong ----------------
// A: tf32 u32 [M,K]; Bt: tf32 u32 [Nc,K] (pre-transposed); C fp32 (or tf32 bits if TFOUT).
#define ASTR 36                       // row stride in u32; ldmatrix conflict-free
#define TILE_U32 (128 * ASTR)
#define STAGE_U32 (2 * TILE_U32)
#define GEMM_SMEM_BYTES (2 * STAGE_U32 * 4)

__device__ __forceinline__ void ldsm4(unsigned* r, unsigned addr)
{
    asm volatile("ldmatrix.sync.aligned.m8n8.x4.shared.b16 {%0,%1,%2,%3}, [%4];"
                 : "=r"(r[0]), "=r"(r[1]), "=r"(r[2]), "=r"(r[3]) : "r"(addr));
}

__device__ __forceinline__ void mma_tf32(float* c, const unsigned* a, const unsigned* b)
{
    asm volatile(
        "mma.sync.aligned.m16n8k8.row.col.f32.tf32.tf32.f32 "
        "{%0,%1,%2,%3}, {%4,%5,%6,%7}, {%8,%9}, {%0,%1,%2,%3};\n"
        : "+f"(c[0]), "+f"(c[1]), "+f"(c[2]), "+f"(c[3])
        : "r"(a[0]), "r"(a[1]), "r"(a[2]), "r"(a[3]), "r"(b[0]), "r"(b[1]));
}

template <bool RELU, bool BIAS, bool STATS, bool TFOUT>
__global__ void __launch_bounds__(256, 2)
k_gemm(const unsigned* __restrict__ A, const unsigned* __restrict__ Bt,
       const float* __restrict__ bias, float* __restrict__ C,
       int M, int Nc, int K, double* __restrict__ sums)
{
    extern __shared__ __align__(16) unsigned dsm[];
    __shared__ double sred[256];

    const int tid  = threadIdx.x;
    const int lane = tid & 31;
    const int wid  = tid >> 5;
    const int g    = lane >> 2;
    const int t4   = lane & 3;
    const int warpM = (wid >> 2) * 64;
    const int warpN = (wid & 3) * 32;
    const int rowBase = blockIdx.y * 128;
    const int colBase = blockIdx.x * 128;

    float acc[4][4][4];
#pragma unroll
    for (int i = 0; i < 4; i++)
#pragma unroll
        for (int j = 0; j < 4; j++)
#pragma unroll
            for (int k = 0; k < 4; k++) acc[i][j][k] = 0.f;

    // cp.async fill mapping: 2 threads per row, 64B each
    const int fR = tid >> 1;
    const int fH = (tid & 1) * 16;        // u32 offset within the 32-u32 row
    const unsigned smBase = (unsigned)__cvta_generic_to_shared(dsm);
    const unsigned aDst0 = smBase + (unsigned)((fR * ASTR + fH) * 4);
    const unsigned bDst0 = smBase + (unsigned)((TILE_U32 + fR * ASTR + fH) * 4);
    const bool aOk = (rowBase + fR) < M;
    const int  aSz = aOk ? 16 : 0;
    const unsigned* aSrcRow = A + (size_t)(aOk ? rowBase + fR : 0) * K + fH;
    const unsigned* bSrcRow = Bt + (size_t)(colBase + fR) * K + fH;

    // ldmatrix lane base addresses (stage 0)
    const unsigned aBase0 = smBase + (((warpM + (lane & 7) + ((lane >> 3) & 1) * 8) * ASTR)
                                      + ((lane >> 4) & 1) * 4) * 4u;
    const unsigned bBase0 = smBase + (TILE_U32 + ((warpN + (lane & 7)) * ASTR) + (lane >> 3) * 4) * 4u;

    auto FILL = [&](int s, int k0) {
        unsigned off = (unsigned)(s * STAGE_U32 * 4);
        const unsigned* as = aSrcRow + k0;
        const unsigned* bs = bSrcRow + k0;
#pragma unroll
        for (int j = 0; j < 4; j++)
            asm volatile("cp.async.cg.shared.global [%0], [%1], 16, %2;"
                         :: "r"(aDst0 + off + j * 16), "l"(as + j * 4), "r"(aSz) : "memory");
#pragma unroll
        for (int j = 0; j < 4; j++)
            asm volatile("cp.async.cg.shared.global [%0], [%1], 16;"
                         :: "r"(bDst0 + off + j * 16), "l"(bs + j * 4) : "memory");
        asm volatile("cp.async.commit_group;" ::: "memory");
    };

    auto MMA = [&](int s) {
        unsigned aB = aBase0 + (unsigned)(s * STAGE_U32 * 4);
        unsigned bB = bBase0 + (unsigned)(s * STAGE_U32 * 4);
#pragma unroll
        for (int kbp = 0; kbp < 2; kbp++) {
            unsigned bf[4][4];
#pragma unroll
            for (int nt = 0; nt < 4; nt++)
                ldsm4(bf[nt], bB + (unsigned)((nt * 8 * ASTR + kbp * 16) * 4));
#pragma unroll
            for (int kk = 0; kk < 2; kk++) {
                int kb = kbp * 2 + kk;
                unsigned af[4][4];
#pragma unroll
                for (int mt = 0; mt < 4; mt++)
                    ldsm4(af[mt], aB + (unsigned)((mt * 16 * ASTR + kb * 8) * 4));
#pragma unroll
                for (int nt = 0; nt < 4; nt++)
#pragma unroll
                    for (int mt = 0; mt < 4; mt++)
                        mma_tf32(acc[mt][nt], af[mt], &bf[nt][kk * 2]);
            }
        }
    };

    // -------- pipelined mainloop --------
    FILL(0, 0);
    int stage = 0;
    for (int k0 = 0; k0 < K; k0 += 32) {
        if (k0 + 32 < K) {
            FILL(stage ^ 1, k0 + 32);
            asm volatile("cp.async.wait_group 1;" ::: "memory");
        } else {
            asm volatile("cp.async.wait_group 0;" ::: "memory");
        }
        __syncthreads();
        MMA(stage);
        __syncthreads();
        stage ^= 1;
    }

    // ---- epilogue ----
    double s1 = 0.0, s2 = 0.0;
#pragma unroll
    for (int nt = 0; nt < 4; nt++) {
        int col = colBase + warpN + nt * 8 + 2 * t4;
        float2 bv = make_float2(0.f, 0.f);
        if (BIAS) bv = *reinterpret_cast<const float2*>(bias + col);
#pragma unroll
        for (int mt = 0; mt < 4; mt++) {
            int r0 = rowBase + warpM + mt * 16 + g;
            float c0 = acc[mt][nt][0] + bv.x;
            float c1 = acc[mt][nt][1] + bv.y;
            float c2 = acc[mt][nt][2] + bv.x;
            float c3 = acc[mt][nt][3] + bv.y;
            if (RELU) {
                c0 = fmaxf(c0, 0.f); c1 = fmaxf(c1, 0.f);
                c2 = fmaxf(c2, 0.f); c3 = fmaxf(c3, 0.f);
            }
            float o0 = c0, o1 = c1, o2 = c2, o3 = c3;
            if (TFOUT) {
                o0 = __uint_as_float(f2tf32(c0)); o1 = __uint_as_float(f2tf32(c1));
                o2 = __uint_as_float(f2tf32(c2)); o3 = __uint_as_float(f2tf32(c3));
            }
            if (r0 < M) {
                *reinterpret_cast<float2*>(C + (size_t)r0 * Nc + col) = make_float2(o0, o1);
                if (STATS) { s1 += (double)c0 + (double)c1;
                             s2 += (double)c0 * c0 + (double)c1 * c1; }
            }
            if (r0 + 8 < M) {
                *reinterpret_cast<float2*>(C + (size_t)(r0 + 8) * Nc + col) = make_float2(o2, o3);
                if (STATS) { s1 += (double)c2 + (double)c3;
                             s2 += (double)c2 * c2 + (double)c3 * c3; }
            }
        }
    }

    if (STATS) {
        sred[tid] = s1; __syncthreads();
        for (int o = 128; o > 0; o >>= 1) { if (tid < o) sred[tid] += sred[tid + o]; __syncthreads(); }
        if (tid == 0) atomicAdd(&sums[0], sred[0]);
        __syncthreads();
        sred[tid] = s2; __syncthreads();
        for (int o = 128; o > 0; o >>= 1) { if (tid < o) sred[tid] += sred[tid + o]; __syncthreads(); }
        if (tid == 0) atomicAdd(&sums[1], sred[0]);
    }
}

// ---------------- conv2 combine: y2 = agg/deg + bl2 + r2 (pr cols 128..255), stats ----------------
__global__ void k_y2(const float* __restrict__ agg, const float* __restrict__ pr,
                     const float* __restrict__ bl2, const float* __restrict__ deg,
                     float* __restrict__ y2)
{
    __shared__ double sred[256];
    double s1 = 0.0, s2 = 0.0;
    const int n = N_NODES * 128;
    for (int idx = blockIdx.x * blockDim.x + threadIdx.x; idx < n; idx += gridDim.x * blockDim.x) {
        int i = idx >> 7, c = idx & 127;
        float y = agg[idx] / fmaxf(deg[i], 1.0f) + bl2[c] + pr[(size_t)i * 256 + 128 + c];
        y2[idx] = y;
        s1 += (double)y; s2 += (double)y * (double)y;
    }
    int tid = threadIdx.x;
    sred[tid] = s1; __syncthreads();
    for (int o = 128; o > 0; o >>= 1) { if (tid < o) sred[tid] += sred[tid + o]; __syncthreads(); }
    if (tid == 0) atomicAdd(&g_sums[2], sred[0]);
    __syncthreads();
    sred[tid] = s2; __syncthreads();
    for (int o = 128; o > 0; o >>= 1) { if (tid < o) sred[tid] += sred[tid + o]; __syncthreads(); }
    if (tid == 0) atomicAdd(&g_sums[3], sred[0]);
}

__global__ void k_finalize(int stage)
{
    double cnt = (stage == 0) ? (double)N_NODES * 256.0 : (double)N_NODES * 128.0;
    int o = stage * 2;
    double mu  = g_sums[o] / cnt;
    double var = g_sums[o + 1] / cnt - mu * mu;
    g_stats[o]     = (float)mu;
    g_stats[o + 1] = (float)(1.0 / sqrt(var + 1e-5));
}

// ---------------- launch ----------------
extern "C" void kernel_launch(void* const* d_in, const int* in_sizes, int n_in,
                              void* d_out, int out_size)
{
    const float* x    = (const float*)d_in[0];
    const void*  ei   =               d_in[1];
    const float* Wl1  = (const float*)d_in[2];
    const float* bl1  = (const float*)d_in[3];
    const float* Wr1  = (const float*)d_in[4];
    const float* ln1w = (const float*)d_in[5];
    const float* ln1b = (const float*)d_in[6];
    const float* W1   = (const float*)d_in[7];
    const float* b1   = (const float*)d_in[8];
    const float* W2   = (const float*)d_in[9];
    const float* b2   = (const float*)d_in[10];
    const float* Wl2  = (const float*)d_in[11];
    const float* bl2  = (const float*)d_in[12];
    const float* Wr2  = (const float*)d_in[13];
    const float* ln2w = (const float*)d_in[14];
    const float* ln2b = (const float*)d_in[15];
    const float* W3   = (const float*)d_in[16];
    const float* b3   = (const float*)d_in[17];
    const float* W4   = (const float*)d_in[18];
    const float* b4   = (const float*)d_in[19];
    float* out = (float*)d_out;

    float *agg, *deg, *y1, *pr, *y2;
    unsigned *a1, *z1, *t1, *h2, *z2, *t3, *bt1, *w1t, *w2t, *blr2, *w3t, *w4t;
    double* sums;
    cudaGetSymbolAddress((void**)&agg,  g_agg);
    cudaGetSymbolAddress((void**)&deg,  g_deg);
    cudaGetSymbolAddress((void**)&a1,   g_a1);
    cudaGetSymbolAddress((void**)&y1,   g_y1);
    cudaGetSymbolAddress((void**)&z1,   g_z1);
    cudaGetSymbolAddress((void**)&t1,   g_t1);
    cudaGetSymbolAddress((void**)&h2,   g_h2);
    cudaGetSymbolAddress((void**)&pr,   g_pr);
    cudaGetSymbolAddress((void**)&y2,   g_y2);
    cudaGetSymbolAddress((void**)&z2,   g_z2);
    cudaGetSymbolAddress((void**)&t3,   g_t3);
    cudaGetSymbolAddress((void**)&bt1,  g_bt1);
    cudaGetSymbolAddress((void**)&w1t,  g_w1t);
    cudaGetSymbolAddress((void**)&w2t,  g_w2t);
    cudaGetSymbolAddress((void**)&blr2, g_blr2);
    cudaGetSymbolAddress((void**)&w3t,  g_w3t);
    cudaGetSymbolAddress((void**)&w4t,  g_w4t);
    cudaGetSymbolAddress((void**)&sums, g_sums);

    cudaFuncSetAttribute(k_gemm<false, true,  true,  false>, cudaFuncAttributeMaxDynamicSharedMemorySize, GEMM_SMEM_BYTES);
    cudaFuncSetAttribute(k_gemm<true,  true,  false, true >, cudaFuncAttributeMaxDynamicSharedMemorySize, GEMM_SMEM_BYTES);
    cudaFuncSetAttribute(k_gemm<false, false, false, false>, cudaFuncAttributeMaxDynamicSharedMemorySize, GEMM_SMEM_BYTES);
    cudaFuncSetAttribute(k_gemm<false, true,  false, false>, cudaFuncAttributeMaxDynamicSharedMemorySize, GEMM_SMEM_BYTES);

    const int M = N_NODES;
    const unsigned gy = (M + 127) / 128;
    const int scatterBlocks = (N_EDGES * 32 + 255) / 256;

    // --- weight prep (transposed tf32) ---
    k_wt<<<(128 * 256 + 255) / 256, 256>>>(Wl1, bt1, 128, 256, 256);
    k_wt<<<(128 * 256 + 255) / 256, 256>>>(Wr1, bt1 + 128, 128, 256, 256);
    k_wt<<<(256 * 512 + 255) / 256, 256>>>(W1, w1t, 256, 512, 256);
    k_wt<<<(512 * 256 + 255) / 256, 256>>>(W2, w2t, 512, 256, 512);
    k_wt<<<(256 * 128 + 255) / 256, 256>>>(Wl2, blr2, 256, 128, 256);
    k_wt<<<(256 * 128 + 255) / 256, 256>>>(Wr2, blr2 + 128 * 256, 256, 128, 256);
    k_wt<<<(128 * 256 + 255) / 256, 256>>>(W3, w3t, 128, 256, 128);
    k_wt<<<(256 * 128 + 255) / 256, 256>>>(W4, w4t, 256, 128, 256);

    // --- conv1 ---
    k_init<<<1, 1>>>((const unsigned long long*)ei);
    k_zerof<<<(N_NODES * 128 + 255) / 256, 256>>>(agg, N_NODES * 128);
    k_zerof<<<(N_NODES + 255) / 256, 256>>>(deg, N_NODES);
    k_scatter<<<scatterBlocks, 256>>>(ei, x, 128, agg, deg, 1);
    k_prep1<<<(N_NODES * 32 + 255) / 256, 256>>>(agg, x, deg, a1);
    // y1 = A1 @ Bt1 + bl1, + LN1 stats
    k_gemm<false, true, true, false><<<dim3(2, gy), 256, GEMM_SMEM_BYTES>>>(
        a1, bt1, bl1, y1, M, 256, 256, sums);
    k_finalize<<<1, 1>>>(0);
    // z1 = tf32(relu(LN1(y1)))
    k_lnrelu<<<(N_NODES * 64 + 255) / 256, 256>>>(y1, z1, ln1w, ln1b, 255, 0, N_NODES * 64);
    // t1 = tf32(relu(z1 @ W1t + b1))
    k_gemm<true, true, false, true><<<dim3(4, gy), 256, GEMM_SMEM_BYTES>>>(
        z1, w1t, b1, (float*)t1, M, 512, 256, nullptr);
    // h2 = tf32(relu(t1 @ W2t + b2))
    k_gemm<true, true, false, true><<<dim3(2, gy), 256, GEMM_SMEM_BYTES>>>(
        t1, w2t, b2, (float*)h2, M, 256, 512, nullptr);

    // --- conv2 (projected-first): pr = h2 @ [Wl2 | Wr2], fp32 ---
    k_gemm<false, false, false, false><<<dim3(2, gy), 256, GEMM_SMEM_BYTES>>>(
        h2, blr2, nullptr, pr, M, 256, 256, nullptr);
    k_zerof<<<(N_NODES * 128 + 255) / 256, 256>>>(agg, N_NODES * 128);
    k_scatter<<<scatterBlocks, 256>>>(ei, pr, 256, agg, deg, 0);
    k_y2<<<1024, 256>>>(agg, pr, bl2, deg, y2);
    k_finalize<<<1, 1>>>(1);
    // z2 = tf32(relu(LN2(y2)))
    k_lnrelu<<<(N_NODES * 32 + 255) / 256, 256>>>(y2, z2, ln2w, ln2b, 127, 2, N_NODES * 32);
    // t3 = tf32(relu(z2 @ W3t + b3))
    k_gemm<true, true, false, true><<<dim3(2, gy), 256, GEMM_SMEM_BYTES>>>(
        z2, w3t, b3, (float*)t3, M, 256, 128, nullptr);
    // out = t3 @ W4t + b4
    k_gemm<false, true, false, false><<<dim3(1, gy), 256, GEMM_SMEM_BYTES>>>(
        t3, w4t, b4, out, M, 128, 256, nullptr);
}

// round 7
// speedup vs baseline: 1.2743x; 1.1182x over previous
#include <cuda_runtime.h>

#define N_NODES 50000
#define N_EDGES 800000

// ---------------- scratch (static device globals; no allocation) ----------------
static __device__ float    g_agg[(size_t)N_NODES * 128];
static __device__ float    g_deg[N_NODES];
static __device__ unsigned g_a1 [(size_t)N_NODES * 256];   // tf32: [agg/deg | x]
static __device__ float    g_y1 [(size_t)N_NODES * 256];
static __device__ unsigned g_z1 [(size_t)N_NODES * 256];   // tf32 relu(LN1(y1))
static __device__ unsigned g_t1 [(size_t)N_NODES * 512];   // tf32
static __device__ unsigned g_h2 [(size_t)N_NODES * 256];   // tf32
static __device__ float    g_pr [(size_t)N_NODES * 256];   // [p | r2] fp32
static __device__ float    g_y2 [(size_t)N_NODES * 128];
static __device__ unsigned g_z2 [(size_t)N_NODES * 128];   // tf32 relu(LN2(y2))
static __device__ unsigned g_t3 [(size_t)N_NODES * 256];   // tf32
// transposed tf32 weights [n][k]
static __device__ unsigned g_bt1 [256 * 256];
static __device__ unsigned g_w1t [512 * 256];
static __device__ unsigned g_w2t [256 * 512];
static __device__ unsigned g_blr2[256 * 256];
static __device__ unsigned g_w3t [256 * 128];
static __device__ unsigned g_w4t [128 * 256];
static __device__ double   g_sums[4];
static __device__ float    g_stats[4];   // mu1, rsigma1, mu2, rsigma2
static __device__ int      g_is64;

__device__ __forceinline__ unsigned f2tf32(float v)
{
    unsigned u;
    asm("cvt.rna.tf32.f32 %0, %1;" : "=r"(u) : "f"(v));
    return u;
}

// ---------------- init ----------------
__global__ void k_init(const unsigned long long* __restrict__ ei)
{
    int ok = 1;
#pragma unroll
    for (int i = 0; i < 16; i++)
        ok &= ((ei[i] >> 32) == 0ull) ? 1 : 0;
    g_is64 = ok;
    g_sums[0] = 0.0; g_sums[1] = 0.0; g_sums[2] = 0.0; g_sums[3] = 0.0;
}

__global__ void k_zerof(float* __restrict__ p, int n)
{
    int i = blockIdx.x * blockDim.x + threadIdx.x;
    if (i < n) p[i] = 0.0f;
}

// ---------------- weight transpose + tf32 convert ----------------
__global__ void k_wt(const float* __restrict__ src, unsigned* __restrict__ dst,
                     int K, int N, int stride)
{
    int idx = blockIdx.x * blockDim.x + threadIdx.x;
    if (idx >= K * N) return;
    int k = idx / N, n = idx % N;
    dst[n * stride + k] = f2tf32(src[idx]);
}

// ---------------- edge scatter: warp per edge, float4 vector-RED per lane ----------------
__global__ void k_scatter(const void* __restrict__ ei, const float* __restrict__ feat,
                          int fstride, float* __restrict__ agg, float* __restrict__ deg,
                          int addDeg)
{
    int gw   = (blockIdx.x * blockDim.x + threadIdx.x) >> 5;
    int lane = threadIdx.x & 31;
    if (gw >= N_EDGES) return;

    long long s, d;
    if (g_is64) {
        const long long* p = (const long long*)ei;
        s = p[gw]; d = p[N_EDGES + gw];
    } else {
        const int* p = (const int*)ei;
        s = p[gw];  d = p[N_EDGES + gw];
    }

    float4 v = *reinterpret_cast<const float4*>(feat + (size_t)s * fstride + lane * 4);
    float* dp = agg + (size_t)d * 128 + lane * 4;
    asm volatile("red.global.add.v4.f32 [%0], {%1,%2,%3,%4};"
                 :: "l"(dp), "f"(v.x), "f"(v.y), "f"(v.z), "f"(v.w) : "memory");
    if (addDeg && lane == 0) atomicAdd(deg + d, 1.0f);
}

// ---------------- conv1 A prep: A1 = tf32([agg/deg | x]) ----------------
__global__ void k_prep1(const float* __restrict__ agg, const float* __restrict__ x,
                        const float* __restrict__ deg, unsigned* __restrict__ A1)
{
    int idx = blockIdx.x * blockDim.x + threadIdx.x;
    if (idx >= N_NODES * 32) return;
    int i = idx >> 5, c = (idx & 31) * 4;
    float inv = 1.0f / fmaxf(deg[i], 1.0f);
    float4 a = *reinterpret_cast<const float4*>(agg + (size_t)i * 128 + c);
    float4 xv = *reinterpret_cast<const float4*>(x + (size_t)i * 128 + c);
    uint4 ta, tx;
    ta.x = f2tf32(a.x * inv); ta.y = f2tf32(a.y * inv);
    ta.z = f2tf32(a.z * inv); ta.w = f2tf32(a.w * inv);
    tx.x = f2tf32(xv.x); tx.y = f2tf32(xv.y); tx.z = f2tf32(xv.z); tx.w = f2tf32(xv.w);
    *reinterpret_cast<uint4*>(A1 + (size_t)i * 256 + c) = ta;
    *reinterpret_cast<uint4*>(A1 + (size_t)i * 256 + 128 + c) = tx;
}

// ---------------- LN+ReLU -> tf32 ----------------
__global__ void k_lnrelu(const float* __restrict__ src, unsigned* __restrict__ dst,
                         const float* __restrict__ w, const float* __restrict__ b,
                         int Cmask, int statOff, int total4)
{
    int idx = blockIdx.x * blockDim.x + threadIdx.x;
    if (idx >= total4) return;
    float mu = g_stats[statOff], rs = g_stats[statOff + 1];
    int c = (idx * 4) & Cmask;
    float4 v = reinterpret_cast<const float4*>(src)[idx];
    float4 w4 = *reinterpret_cast<const float4*>(w + c);
    float4 b4 = *reinterpret_cast<const float4*>(b + c);
    uint4 o;
    o.x = f2tf32(fmaxf((v.x - mu) * rs * w4.x + b4.x, 0.f));
    o.y = f2tf32(fmaxf((v.y - mu) * rs * w4.y + b4.y, 0.f));
    o.z = f2tf32(fmaxf((v.z - mu) * rs * w4.z + b4.z, 0.f));
    o.w = f2tf32(fmaxf((v.w - mu) * rs * w4.w + b4.w, 0.f));
    reinterpret_cast<uint4*>(dst)[idx] = o;
}

// ---------------- TF32 tensor-core GEMM, 3-stage cp.async ring, XOR swizzle ----------------
// smem row = 32 u32 (128B) = 8 chunks of 16B; chunk index is XORed with (row & 7).
// Conflict-free for cp.async fills and all ldmatrix phases.
#define TILE_U32 (128 * 32)
#define STAGE_U32 (2 * TILE_U32)
#define NSTAGE 3
#define GEMM_SMEM_BYTES (NSTAGE * STAGE_U32 * 4)   // 98304

__device__ __forceinline__ void ldsm4(unsigned* r, unsigned addr)
{
    asm volatile("ldmatrix.sync.aligned.m8n8.x4.shared.b16 {%0,%1,%2,%3}, [%4];"
                 : "=r"(r[0]), "=r"(r[1]), "=r"(r[2]), "=r"(r[3]) : "r"(addr));
}

__device__ __forceinline__ void mma_tf32(float* c, const unsigned* a, const unsigned* b)
{
    asm volatile(
        "mma.sync.aligned.m16n8k8.row.col.f32.tf32.tf32.f32 "
        "{%0,%1,%2,%3}, {%4,%5,%6,%7}, {%8,%9}, {%0,%1,%2,%3};\n"
        : "+f"(c[0]), "+f"(c[1]), "+f"(c[2]), "+f"(c[3])
        : "r"(a[0]), "r"(a[1]), "r"(a[2]), "r"(a[3]), "r"(b[0]), "r"(b[1]));
}

template <bool RELU, bool BIAS, bool STATS, bool TFOUT>
__global__ void __launch_bounds__(256, 2)
k_gemm(const unsigned* __restrict__ A, const unsigned* __restrict__ Bt,
       const float* __restrict__ bias, float* __restrict__ C,
       int M, int Nc, int K, double* __restrict__ sums)
{
    extern __shared__ __align__(16) unsigned dsm[];
    __shared__ double sred[256];

    const int tid  = threadIdx.x;
    const int lane = tid & 31;
    const int wid  = tid >> 5;
    const int g    = lane >> 2;
    const int t4   = lane & 3;
    const int warpM = (wid >> 2) * 64;
    const int warpN = (wid & 3) * 32;
    const int rowBase = blockIdx.y * 128;
    const int colBase = blockIdx.x * 128;

    float acc[4][4][4];
#pragma unroll
    for (int i = 0; i < 4; i++)
#pragma unroll
        for (int j = 0; j < 4; j++)
#pragma unroll
            for (int k = 0; k < 4; k++) acc[i][j][k] = 0.f;

    // ---- fill mapping: 2 threads per row, 4 chunks (16B) each, XOR swizzle ----
    const int fR  = tid >> 1;
    const int fXr = fR & 7;
    const int fC0 = (tid & 1) * 4;
    const unsigned smBase = (unsigned)__cvta_generic_to_shared(dsm);
    const unsigned aRowDst = smBase + (unsigned)(fR * 128);
    const unsigned bRowDst = smBase + (unsigned)(TILE_U32 * 4 + fR * 128);
    const bool aOk = (rowBase + fR) < M;
    const int  aSz = aOk ? 16 : 0;
    const unsigned* aSrcRow = A + (size_t)(aOk ? rowBase + fR : 0) * K + fC0 * 4;
    const unsigned* bSrcRow = Bt + (size_t)(colBase + fR) * K + fC0 * 4;

    // ---- ldmatrix lane mapping (XOR swizzle) ----
    const int aRowL = warpM + (lane & 7) + ((lane >> 3) & 1) * 8;
    const unsigned aRow0 = smBase + (unsigned)(aRowL * 128);
    const int xrA = lane & 7;
    const int cA  = (lane >> 4) & 1;
    const int bRowL = warpN + (lane & 7);
    const unsigned bRow0 = smBase + (unsigned)(TILE_U32 * 4 + bRowL * 128);
    const int xrB = lane & 7;
    const int cB  = lane >> 3;

    auto FILL = [&](int s, int k0) {
        unsigned off = (unsigned)(s * STAGE_U32 * 4);
        const unsigned* as = aSrcRow + k0;
        const unsigned* bs = bSrcRow + k0;
#pragma unroll
        for (int j = 0; j < 4; j++) {
            unsigned dA = aRowDst + off + (unsigned)((((fC0 + j) ^ fXr)) << 4);
            asm volatile("cp.async.cg.shared.global [%0], [%1], 16, %2;"
                         :: "r"(dA), "l"(as + j * 4), "r"(aSz) : "memory");
        }
#pragma unroll
        for (int j = 0; j < 4; j++) {
            unsigned dB = bRowDst + off + (unsigned)((((fC0 + j) ^ fXr)) << 4);
            asm volatile("cp.async.cg.shared.global [%0], [%1], 16;"
                         :: "r"(dB), "l"(bs + j * 4) : "memory");
        }
        asm volatile("cp.async.commit_group;" ::: "memory");
    };

    auto MMA = [&](int s) {
        unsigned off = (unsigned)(s * STAGE_U32 * 4);
#pragma unroll
        for (int kbp = 0; kbp < 2; kbp++) {
            unsigned bf[4][4];
#pragma unroll
            for (int nt = 0; nt < 4; nt++)
                ldsm4(bf[nt], bRow0 + off + (unsigned)(nt * 8 * 128)
                              + (unsigned)(((cB + 4 * kbp) ^ xrB) << 4));
#pragma unroll
            for (int kk = 0; kk < 2; kk++) {
                int kb = kbp * 2 + kk;
                unsigned af[4][4];
#pragma unroll
                for (int mt = 0; mt < 4; mt++)
                    ldsm4(af[mt], aRow0 + off + (unsigned)(mt * 16 * 128)
                                  + (unsigned)(((cA + 2 * kb) ^ xrA) << 4));
#pragma unroll
                for (int nt = 0; nt < 4; nt++)
#pragma unroll
                    for (int mt = 0; mt < 4; mt++)
                        mma_tf32(acc[mt][nt], af[mt], &bf[nt][kk * 2]);
            }
        }
    };

    // -------- 3-stage pipelined mainloop, one sync per iter --------
    // Ring indices tracked incrementally (branch-free wrap, correct for any T).
    const int T = K >> 5;
    FILL(0, 0);
    if (T > 1) FILL(1, 32);
    int curS = 0;                       // stage to consume at iter i
    int fillS = (T > 1) ? 2 : 1;        // next stage to fill
    if (fillS >= NSTAGE) fillS -= NSTAGE;
    for (int i = 0; i < T; i++) {
        if (i + 1 < T) { asm volatile("cp.async.wait_group 1;" ::: "memory"); }
        else           { asm volatile("cp.async.wait_group 0;" ::: "memory"); }
        __syncthreads();
        if (i + 2 < T) {
            FILL(fillS, (i + 2) * 32);
            if (++fillS == NSTAGE) fillS = 0;
        }
        MMA(curS);
        if (++curS == NSTAGE) curS = 0;
    }

    // ---- epilogue ----
    double s1 = 0.0, s2 = 0.0;
#pragma unroll
    for (int nt = 0; nt < 4; nt++) {
        int col = colBase + warpN + nt * 8 + 2 * t4;
        float2 bv = make_float2(0.f, 0.f);
        if (BIAS) bv = *reinterpret_cast<const float2*>(bias + col);
#pragma unroll
        for (int mt = 0; mt < 4; mt++) {
            int r0 = rowBase + warpM + mt * 16 + g;
            float c0 = acc[mt][nt][0] + bv.x;
            float c1 = acc[mt][nt][1] + bv.y;
            float c2 = acc[mt][nt][2] + bv.x;
            float c3 = acc[mt][nt][3] + bv.y;
            if (RELU) {
                c0 = fmaxf(c0, 0.f); c1 = fmaxf(c1, 0.f);
                c2 = fmaxf(c2, 0.f); c3 = fmaxf(c3, 0.f);
            }
            float o0 = c0, o1 = c1, o2 = c2, o3 = c3;
            if (TFOUT) {
                o0 = __uint_as_float(f2tf32(c0)); o1 = __uint_as_float(f2tf32(c1));
                o2 = __uint_as_float(f2tf32(c2)); o3 = __uint_as_float(f2tf32(c3));
            }
            if (r0 < M) {
                *reinterpret_cast<float2*>(C + (size_t)r0 * Nc + col) = make_float2(o0, o1);
                if (STATS) { s1 += (double)c0 + (double)c1;
                             s2 += (double)c0 * c0 + (double)c1 * c1; }
            }
            if (r0 + 8 < M) {
                *reinterpret_cast<float2*>(C + (size_t)(r0 + 8) * Nc + col) = make_float2(o2, o3);
                if (STATS) { s1 += (double)c2 + (double)c3;
                             s2 += (double)c2 * c2 + (double)c3 * c3; }
            }
        }
    }

    if (STATS) {
        sred[tid] = s1; __syncthreads();
        for (int o = 128; o > 0; o >>= 1) { if (tid < o) sred[tid] += sred[tid + o]; __syncthreads(); }
        if (tid == 0) atomicAdd(&sums[0], sred[0]);
        __syncthreads();
        sred[tid] = s2; __syncthreads();
        for (int o = 128; o > 0; o >>= 1) { if (tid < o) sred[tid] += sred[tid + o]; __syncthreads(); }
        if (tid == 0) atomicAdd(&sums[1], sred[0]);
    }
}

// ---------------- conv2 combine ----------------
__global__ void k_y2(const float* __restrict__ agg, const float* __restrict__ pr,
                     const float* __restrict__ bl2, const float* __restrict__ deg,
                     float* __restrict__ y2)
{
    __shared__ double sred[256];
    double s1 = 0.0, s2 = 0.0;
    const int n = N_NODES * 128;
    for (int idx = blockIdx.x * blockDim.x + threadIdx.x; idx < n; idx += gridDim.x * blockDim.x) {
        int i = idx >> 7, c = idx & 127;
        float y = agg[idx] / fmaxf(deg[i], 1.0f) + bl2[c] + pr[(size_t)i * 256 + 128 + c];
        y2[idx] = y;
        s1 += (double)y; s2 += (double)y * (double)y;
    }
    int tid = threadIdx.x;
    sred[tid] = s1; __syncthreads();
    for (int o = 128; o > 0; o >>= 1) { if (tid < o) sred[tid] += sred[tid + o]; __syncthreads(); }
    if (tid == 0) atomicAdd(&g_sums[2], sred[0]);
    __syncthreads();
    sred[tid] = s2; __syncthreads();
    for (int o = 128; o > 0; o >>= 1) { if (tid < o) sred[tid] += sred[tid + o]; __syncthreads(); }
    if (tid == 0) atomicAdd(&g_sums[3], sred[0]);
}

__global__ void k_finalize(int stage)
{
    double cnt = (stage == 0) ? (double)N_NODES * 256.0 : (double)N_NODES * 128.0;
    int o = stage * 2;
    double mu  = g_sums[o] / cnt;
    double var = g_sums[o + 1] / cnt - mu * mu;
    g_stats[o]     = (float)mu;
    g_stats[o + 1] = (float)(1.0 / sqrt(var + 1e-5));
}

// ---------------- launch ----------------
extern "C" void kernel_launch(void* const* d_in, const int* in_sizes, int n_in,
                              void* d_out, int out_size)
{
    const float* x    = (const float*)d_in[0];
    const void*  ei   =               d_in[1];
    const float* Wl1  = (const float*)d_in[2];
    const float* bl1  = (const float*)d_in[3];
    const float* Wr1  = (const float*)d_in[4];
    const float* ln1w = (const float*)d_in[5];
    const float* ln1b = (const float*)d_in[6];
    const float* W1   = (const float*)d_in[7];
    const float* b1   = (const float*)d_in[8];
    const float* W2   = (const float*)d_in[9];
    const float* b2   = (const float*)d_in[10];
    const float* Wl2  = (const float*)d_in[11];
    const float* bl2  = (const float*)d_in[12];
    const float* Wr2  = (const float*)d_in[13];
    const float* ln2w = (const float*)d_in[14];
    const float* ln2b = (const float*)d_in[15];
    const float* W3   = (const float*)d_in[16];
    const float* b3   = (const float*)d_in[17];
    const float* W4   = (const float*)d_in[18];
    const float* b4   = (const float*)d_in[19];
    float* out = (float*)d_out;

    float *agg, *deg, *y1, *pr, *y2;
    unsigned *a1, *z1, *t1, *h2, *z2, *t3, *bt1, *w1t, *w2t, *blr2, *w3t, *w4t;
    double* sums;
    cudaGetSymbolAddress((void**)&agg,  g_agg);
    cudaGetSymbolAddress((void**)&deg,  g_deg);
    cudaGetSymbolAddress((void**)&a1,   g_a1);
    cudaGetSymbolAddress((void**)&y1,   g_y1);
    cudaGetSymbolAddress((void**)&z1,   g_z1);
    cudaGetSymbolAddress((void**)&t1,   g_t1);
    cudaGetSymbolAddress((void**)&h2,   g_h2);
    cudaGetSymbolAddress((void**)&pr,   g_pr);
    cudaGetSymbolAddress((void**)&y2,   g_y2);
    cudaGetSymbolAddress((void**)&z2,   g_z2);
    cudaGetSymbolAddress((void**)&t3,   g_t3);
    cudaGetSymbolAddress((void**)&bt1,  g_bt1);
    cudaGetSymbolAddress((void**)&w1t,  g_w1t);
    cudaGetSymbolAddress((void**)&w2t,  g_w2t);
    cudaGetSymbolAddress((void**)&blr2, g_blr2);
    cudaGetSymbolAddress((void**)&w3t,  g_w3t);
    cudaGetSymbolAddress((void**)&w4t,  g_w4t);
    cudaGetSymbolAddress((void**)&sums, g_sums);

    cudaFuncSetAttribute(k_gemm<false, true,  true,  false>, cudaFuncAttributeMaxDynamicSharedMemorySize, GEMM_SMEM_BYTES);
    cudaFuncSetAttribute(k_gemm<true,  true,  false, true >, cudaFuncAttributeMaxDynamicSharedMemorySize, GEMM_SMEM_BYTES);
    cudaFuncSetAttribute(k_gemm<false, false, false, false>, cudaFuncAttributeMaxDynamicSharedMemorySize, GEMM_SMEM_BYTES);
    cudaFuncSetAttribute(k_gemm<false, true,  false, false>, cudaFuncAttributeMaxDynamicSharedMemorySize, GEMM_SMEM_BYTES);

    const int M = N_NODES;
    const unsigned gy = (M + 127) / 128;
    const int scatterBlocks = (N_EDGES * 32 + 255) / 256;

    // --- weight prep (transposed tf32) ---
    k_wt<<<(128 * 256 + 255) / 256, 256>>>(Wl1, bt1, 128, 256, 256);
    k_wt<<<(128 * 256 + 255) / 256, 256>>>(Wr1, bt1 + 128, 128, 256, 256);
    k_wt<<<(256 * 512 + 255) / 256, 256>>>(W1, w1t, 256, 512, 256);
    k_wt<<<(512 * 256 + 255) / 256, 256>>>(W2, w2t, 512, 256, 512);
    k_wt<<<(256 * 128 + 255) / 256, 256>>>(Wl2, blr2, 256, 128, 256);
    k_wt<<<(256 * 128 + 255) / 256, 256>>>(Wr2, blr2 + 128 * 256, 256, 128, 256);
    k_wt<<<(128 * 256 + 255) / 256, 256>>>(W3, w3t, 128, 256, 128);
    k_wt<<<(256 * 128 + 255) / 256, 256>>>(W4, w4t, 256, 128, 256);

    // --- conv1 ---
    k_init<<<1, 1>>>((const unsigned long long*)ei);
    k_zerof<<<(N_NODES * 128 + 255) / 256, 256>>>(agg, N_NODES * 128);
    k_zerof<<<(N_NODES + 255) / 256, 256>>>(deg, N_NODES);
    k_scatter<<<scatterBlocks, 256>>>(ei, x, 128, agg, deg, 1);
    k_prep1<<<(N_NODES * 32 + 255) / 256, 256>>>(agg, x, deg, a1);
    k_gemm<false, true, true, false><<<dim3(2, gy), 256, GEMM_SMEM_BYTES>>>(
        a1, bt1, bl1, y1, M, 256, 256, sums);
    k_finalize<<<1, 1>>>(0);
    k_lnrelu<<<(N_NODES * 64 + 255) / 256, 256>>>(y1, z1, ln1w, ln1b, 255, 0, N_NODES * 64);
    k_gemm<true, true, false, true><<<dim3(4, gy), 256, GEMM_SMEM_BYTES>>>(
        z1, w1t, b1, (float*)t1, M, 512, 256, nullptr);
    k_gemm<true, true, false, true><<<dim3(2, gy), 256, GEMM_SMEM_BYTES>>>(
        t1, w2t, b2, (float*)h2, M, 256, 512, nullptr);

    // --- conv2 (projected-first): pr = h2 @ [Wl2 | Wr2] ---
    k_gemm<false, false, false, false><<<dim3(2, gy), 256, GEMM_SMEM_BYTES>>>(
        h2, blr2, nullptr, pr, M, 256, 256, nullptr);
    k_zerof<<<(N_NODES * 128 + 255) / 256, 256>>>(agg, N_NODES * 128);
    k_scatter<<<scatterBlocks, 256>>>(ei, pr, 256, agg, deg, 0);
    k_y2<<<1024, 256>>>(agg, pr, bl2, deg, y2);
    k_finalize<<<1, 1>>>(1);
    k_lnrelu<<<(N_NODES * 32 + 255) / 256, 256>>>(y2, z2, ln2w, ln2b, 127, 2, N_NODES * 32);
    k_gemm<true, true, false, true><<<dim3(2, gy), 256, GEMM_SMEM_BYTES>>>(
        z2, w3t, b3, (float*)t3, M, 256, 128, nullptr);
    k_gemm<false, true, false, false><<<dim3(1, gy), 256, GEMM_SMEM_BYTES>>>(
        t3, w4t, b4, out, M, 128, 256, nullptr);
}

// round 8
// speedup vs baseline: 1.2987x; 1.0192x over previous
#include <cuda_runtime.h>

#define N_NODES 50000
#define N_EDGES 800000

// ---------------- scratch (static device globals; no allocation) ----------------
static __device__ float    g_agg[(size_t)N_NODES * 128];
static __device__ float    g_deg[N_NODES];
static __device__ unsigned g_a1 [(size_t)N_NODES * 256];   // tf32: [agg/deg | x]
static __device__ float    g_y1 [(size_t)N_NODES * 256];
static __device__ unsigned g_z1 [(size_t)N_NODES * 256];   // tf32 relu(LN1(y1))
static __device__ unsigned g_t1 [(size_t)N_NODES * 512];   // tf32
static __device__ unsigned g_h2 [(size_t)N_NODES * 256];   // tf32
static __device__ float    g_pr [(size_t)N_NODES * 256];   // [p | r2] fp32
static __device__ float    g_y2 [(size_t)N_NODES * 128];
static __device__ unsigned g_z2 [(size_t)N_NODES * 128];   // tf32 relu(LN2(y2))
static __device__ unsigned g_t3 [(size_t)N_NODES * 256];   // tf32
// transposed tf32 weights [n][k]
static __device__ unsigned g_bt1 [256 * 256];
static __device__ unsigned g_w1t [512 * 256];
static __device__ unsigned g_w2t [256 * 512];
static __device__ unsigned g_blr2[256 * 256];
static __device__ unsigned g_w3t [256 * 128];
static __device__ unsigned g_w4t [128 * 256];
static __device__ double   g_sums[4];
static __device__ int      g_is64;

__device__ __forceinline__ unsigned f2tf32(float v)
{
    unsigned u;
    asm("cvt.rna.tf32.f32 %0, %1;" : "=r"(u) : "f"(v));
    return u;
}

// ---------------- start: is64 detect + sums reset + zero agg & deg (float4) ----------------
#define AGG4 (N_NODES * 128 / 4)          // 1,600,000
#define DEG4 (N_NODES / 4)                // 12,500
__global__ void k_start(const unsigned long long* __restrict__ ei,
                        float4* __restrict__ agg4, float4* __restrict__ deg4)
{
    int idx = blockIdx.x * blockDim.x + threadIdx.x;
    if (idx == 0) {
        int ok = 1;
#pragma unroll
        for (int i = 0; i < 16; i++)
            ok &= ((ei[i] >> 32) == 0ull) ? 1 : 0;
        g_is64 = ok;
        g_sums[0] = 0.0; g_sums[1] = 0.0; g_sums[2] = 0.0; g_sums[3] = 0.0;
    }
    float4 z = make_float4(0.f, 0.f, 0.f, 0.f);
    if (idx < AGG4) agg4[idx] = z;
    else if (idx < AGG4 + DEG4) deg4[idx - AGG4] = z;
}

__global__ void k_zerof4(float4* __restrict__ p)
{
    int i = blockIdx.x * blockDim.x + threadIdx.x;
    if (i < AGG4) p[i] = make_float4(0.f, 0.f, 0.f, 0.f);
}

// ---------------- ALL weight transposes + tf32 convert in ONE kernel ----------------
// dst[n*stride + k] = tf32(src[k*N + n]) per segment
__global__ void k_wtall(const float* __restrict__ Wl1, const float* __restrict__ Wr1,
                        const float* __restrict__ W1,  const float* __restrict__ W2,
                        const float* __restrict__ Wl2, const float* __restrict__ Wr2,
                        const float* __restrict__ W3,  const float* __restrict__ W4,
                        unsigned* __restrict__ bt1, unsigned* __restrict__ w1t,
                        unsigned* __restrict__ w2t, unsigned* __restrict__ blr2,
                        unsigned* __restrict__ w3t, unsigned* __restrict__ w4t)
{
    int i = blockIdx.x * blockDim.x + threadIdx.x;
    if (i < 32768)  { int k = i / 256, n = i % 256; bt1[n * 256 + k] = f2tf32(Wl1[i]); return; }
    i -= 32768;
    if (i < 32768)  { int k = i / 256, n = i % 256; bt1[n * 256 + k + 128] = f2tf32(Wr1[i]); return; }
    i -= 32768;
    if (i < 131072) { int k = i / 512, n = i % 512; w1t[n * 256 + k] = f2tf32(W1[i]); return; }
    i -= 131072;
    if (i < 131072) { int k = i / 256, n = i % 256; w2t[n * 512 + k] = f2tf32(W2[i]); return; }
    i -= 131072;
    if (i < 32768)  { int k = i / 128, n = i % 128; blr2[n * 256 + k] = f2tf32(Wl2[i]); return; }
    i -= 32768;
    if (i < 32768)  { int k = i / 128, n = i % 128; blr2[(n + 128) * 256 + k] = f2tf32(Wr2[i]); return; }
    i -= 32768;
    if (i < 32768)  { int k = i / 256, n = i % 256; w3t[n * 128 + k] = f2tf32(W3[i]); return; }
    i -= 32768;
    if (i < 32768)  { int k = i / 128, n = i % 128; w4t[n * 256 + k] = f2tf32(W4[i]); }
}
#define WTALL_TOTAL (32768 * 6 + 131072 * 2)   // 458752

// ---------------- edge scatter: warp per edge, float4 vector-RED per lane ----------------
__global__ void k_scatter(const void* __restrict__ ei, const float* __restrict__ feat,
                          int fstride, float* __restrict__ agg, float* __restrict__ deg,
                          int addDeg)
{
    int gw   = (blockIdx.x * blockDim.x + threadIdx.x) >> 5;
    int lane = threadIdx.x & 31;
    if (gw >= N_EDGES) return;

    long long s, d;
    if (g_is64) {
        const long long* p = (const long long*)ei;
        s = p[gw]; d = p[N_EDGES + gw];
    } else {
        const int* p = (const int*)ei;
        s = p[gw];  d = p[N_EDGES + gw];
    }

    float4 v = *reinterpret_cast<const float4*>(feat + (size_t)s * fstride + lane * 4);
    float* dp = agg + (size_t)d * 128 + lane * 4;
    asm volatile("red.global.add.v4.f32 [%0], {%1,%2,%3,%4};"
                 :: "l"(dp), "f"(v.x), "f"(v.y), "f"(v.z), "f"(v.w) : "memory");
    if (addDeg && lane == 0) atomicAdd(deg + d, 1.0f);
}

// ---------------- conv1 A prep: A1 = tf32([agg/deg | x]) ----------------
__global__ void k_prep1(const float* __restrict__ agg, const float* __restrict__ x,
                        const float* __restrict__ deg, unsigned* __restrict__ A1)
{
    int idx = blockIdx.x * blockDim.x + threadIdx.x;
    if (idx >= N_NODES * 32) return;
    int i = idx >> 5, c = (idx & 31) * 4;
    float inv = 1.0f / fmaxf(deg[i], 1.0f);
    float4 a = *reinterpret_cast<const float4*>(agg + (size_t)i * 128 + c);
    float4 xv = *reinterpret_cast<const float4*>(x + (size_t)i * 128 + c);
    uint4 ta, tx;
    ta.x = f2tf32(a.x * inv); ta.y = f2tf32(a.y * inv);
    ta.z = f2tf32(a.z * inv); ta.w = f2tf32(a.w * inv);
    tx.x = f2tf32(xv.x); tx.y = f2tf32(xv.y); tx.z = f2tf32(xv.z); tx.w = f2tf32(xv.w);
    *reinterpret_cast<uint4*>(A1 + (size_t)i * 256 + c) = ta;
    *reinterpret_cast<uint4*>(A1 + (size_t)i * 256 + 128 + c) = tx;
}

// ---------------- LN+ReLU -> tf32 (stats computed in-block from g_sums) ----------------
__global__ void k_lnrelu(const float* __restrict__ src, unsigned* __restrict__ dst,
                         const float* __restrict__ w, const float* __restrict__ b,
                         int Cmask, int statOff, double cnt, int total4)
{
    __shared__ float s_mu, s_rs;
    if (threadIdx.x == 0) {
        double mu  = g_sums[statOff] / cnt;
        double var = g_sums[statOff + 1] / cnt - mu * mu;
        s_mu = (float)mu;
        s_rs = (float)(1.0 / sqrt(var + 1e-5));
    }
    __syncthreads();
    int idx = blockIdx.x * blockDim.x + threadIdx.x;
    if (idx >= total4) return;
    float mu = s_mu, rs = s_rs;
    int c = (idx * 4) & Cmask;
    float4 v = reinterpret_cast<const float4*>(src)[idx];
    float4 w4 = *reinterpret_cast<const float4*>(w + c);
    float4 b4 = *reinterpret_cast<const float4*>(b + c);
    uint4 o;
    o.x = f2tf32(fmaxf((v.x - mu) * rs * w4.x + b4.x, 0.f));
    o.y = f2tf32(fmaxf((v.y - mu) * rs * w4.y + b4.y, 0.f));
    o.z = f2tf32(fmaxf((v.z - mu) * rs * w4.z + b4.z, 0.f));
    o.w = f2tf32(fmaxf((v.w - mu) * rs * w4.w + b4.w, 0.f));
    reinterpret_cast<uint4*>(dst)[idx] = o;
}

// ---------------- TF32 tensor-core GEMM, 3-stage cp.async ring, XOR swizzle ----------------
#define TILE_U32 (128 * 32)
#define STAGE_U32 (2 * TILE_U32)
#define NSTAGE 3
#define GEMM_SMEM_BYTES (NSTAGE * STAGE_U32 * 4)   // 98304

__device__ __forceinline__ void ldsm4(unsigned* r, unsigned addr)
{
    asm volatile("ldmatrix.sync.aligned.m8n8.x4.shared.b16 {%0,%1,%2,%3}, [%4];"
                 : "=r"(r[0]), "=r"(r[1]), "=r"(r[2]), "=r"(r[3]) : "r"(addr));
}

__device__ __forceinline__ void mma_tf32(float* c, const unsigned* a, const unsigned* b)
{
    asm volatile(
        "mma.sync.aligned.m16n8k8.row.col.f32.tf32.tf32.f32 "
        "{%0,%1,%2,%3}, {%4,%5,%6,%7}, {%8,%9}, {%0,%1,%2,%3};\n"
        : "+f"(c[0]), "+f"(c[1]), "+f"(c[2]), "+f"(c[3])
        : "r"(a[0]), "r"(a[1]), "r"(a[2]), "r"(a[3]), "r"(b[0]), "r"(b[1]));
}

template <bool RELU, bool BIAS, bool STATS, bool TFOUT>
__global__ void __launch_bounds__(256, 2)
k_gemm(const unsigned* __restrict__ A, const unsigned* __restrict__ Bt,
       const float* __restrict__ bias, float* __restrict__ C,
       int M, int Nc, int K, double* __restrict__ sums)
{
    extern __shared__ __align__(16) unsigned dsm[];
    __shared__ double sred[256];

    const int tid  = threadIdx.x;
    const int lane = tid & 31;
    const int wid  = tid >> 5;
    const int g    = lane >> 2;
    const int t4   = lane & 3;
    const int warpM = (wid >> 2) * 64;
    const int warpN = (wid & 3) * 32;
    const int rowBase = blockIdx.y * 128;
    const int colBase = blockIdx.x * 128;

    float acc[4][4][4];
#pragma unroll
    for (int i = 0; i < 4; i++)
#pragma unroll
        for (int j = 0; j < 4; j++)
#pragma unroll
            for (int k = 0; k < 4; k++) acc[i][j][k] = 0.f;

    // ---- fill mapping: 2 threads per row, 4 chunks (16B) each, XOR swizzle ----
    const int fR  = tid >> 1;
    const int fXr = fR & 7;
    const int fC0 = (tid & 1) * 4;
    const unsigned smBase = (unsigned)__cvta_generic_to_shared(dsm);
    const unsigned aRowDst = smBase + (unsigned)(fR * 128);
    const unsigned bRowDst = smBase + (unsigned)(TILE_U32 * 4 + fR * 128);
    const bool aOk = (rowBase + fR) < M;
    const int  aSz = aOk ? 16 : 0;
    const unsigned* aSrcRow = A + (size_t)(aOk ? rowBase + fR : 0) * K + fC0 * 4;
    const unsigned* bSrcRow = Bt + (size_t)(colBase + fR) * K + fC0 * 4;

    // ---- ldmatrix lane mapping (XOR swizzle) ----
    const int aRowL = warpM + (lane & 7) + ((lane >> 3) & 1) * 8;
    const unsigned aRow0 = smBase + (unsigned)(aRowL * 128);
    const int xrA = lane & 7;
    const int cA  = (lane >> 4) & 1;
    const int bRowL = warpN + (lane & 7);
    const unsigned bRow0 = smBase + (unsigned)(TILE_U32 * 4 + bRowL * 128);
    const int xrB = lane & 7;
    const int cB  = lane >> 3;

    auto FILL = [&](int s, int k0) {
        unsigned off = (unsigned)(s * STAGE_U32 * 4);
        const unsigned* as = aSrcRow + k0;
        const unsigned* bs = bSrcRow + k0;
#pragma unroll
        for (int j = 0; j < 4; j++) {
            unsigned dA = aRowDst + off + (unsigned)((((fC0 + j) ^ fXr)) << 4);
            asm volatile("cp.async.cg.shared.global [%0], [%1], 16, %2;"
                         :: "r"(dA), "l"(as + j * 4), "r"(aSz) : "memory");
        }
#pragma unroll
        for (int j = 0; j < 4; j++) {
            unsigned dB = bRowDst + off + (unsigned)((((fC0 + j) ^ fXr)) << 4);
            asm volatile("cp.async.cg.shared.global [%0], [%1], 16;"
                         :: "r"(dB), "l"(bs + j * 4) : "memory");
        }
        asm volatile("cp.async.commit_group;" ::: "memory");
    };

    auto MMA = [&](int s) {
        unsigned off = (unsigned)(s * STAGE_U32 * 4);
#pragma unroll
        for (int kbp = 0; kbp < 2; kbp++) {
            unsigned bf[4][4];
#pragma unroll
            for (int nt = 0; nt < 4; nt++)
                ldsm4(bf[nt], bRow0 + off + (unsigned)(nt * 8 * 128)
                              + (unsigned)(((cB + 4 * kbp) ^ xrB) << 4));
#pragma unroll
            for (int kk = 0; kk < 2; kk++) {
                int kb = kbp * 2 + kk;
                unsigned af[4][4];
#pragma unroll
                for (int mt = 0; mt < 4; mt++)
                    ldsm4(af[mt], aRow0 + off + (unsigned)(mt * 16 * 128)
                                  + (unsigned)(((cA + 2 * kb) ^ xrA) << 4));
#pragma unroll
                for (int nt = 0; nt < 4; nt++)
#pragma unroll
                    for (int mt = 0; mt < 4; mt++)
                        mma_tf32(acc[mt][nt], af[mt], &bf[nt][kk * 2]);
            }
        }
    };

    // -------- 3-stage pipelined mainloop, one sync per iter --------
    const int T = K >> 5;
    FILL(0, 0);
    if (T > 1) FILL(1, 32);
    int curS = 0;
    int fillS = (T > 1) ? 2 : 1;
    if (fillS >= NSTAGE) fillS -= NSTAGE;
    for (int i = 0; i < T; i++) {
        if (i + 1 < T) { asm volatile("cp.async.wait_group 1;" ::: "memory"); }
        else           { asm volatile("cp.async.wait_group 0;" ::: "memory"); }
        __syncthreads();
        if (i + 2 < T) {
            FILL(fillS, (i + 2) * 32);
            if (++fillS == NSTAGE) fillS = 0;
        }
        MMA(curS);
        if (++curS == NSTAGE) curS = 0;
    }

    // ---- epilogue ----
    double s1 = 0.0, s2 = 0.0;
#pragma unroll
    for (int nt = 0; nt < 4; nt++) {
        int col = colBase + warpN + nt * 8 + 2 * t4;
        float2 bv = make_float2(0.f, 0.f);
        if (BIAS) bv = *reinterpret_cast<const float2*>(bias + col);
#pragma unroll
        for (int mt = 0; mt < 4; mt++) {
            int r0 = rowBase + warpM + mt * 16 + g;
            float c0 = acc[mt][nt][0] + bv.x;
            float c1 = acc[mt][nt][1] + bv.y;
            float c2 = acc[mt][nt][2] + bv.x;
            float c3 = acc[mt][nt][3] + bv.y;
            if (RELU) {
                c0 = fmaxf(c0, 0.f); c1 = fmaxf(c1, 0.f);
                c2 = fmaxf(c2, 0.f); c3 = fmaxf(c3, 0.f);
            }
            float o0 = c0, o1 = c1, o2 = c2, o3 = c3;
            if (TFOUT) {
                o0 = __uint_as_float(f2tf32(c0)); o1 = __uint_as_float(f2tf32(c1));
                o2 = __uint_as_float(f2tf32(c2)); o3 = __uint_as_float(f2tf32(c3));
            }
            if (r0 < M) {
                *reinterpret_cast<float2*>(C + (size_t)r0 * Nc + col) = make_float2(o0, o1);
                if (STATS) { s1 += (double)c0 + (double)c1;
                             s2 += (double)c0 * c0 + (double)c1 * c1; }
            }
            if (r0 + 8 < M) {
                *reinterpret_cast<float2*>(C + (size_t)(r0 + 8) * Nc + col) = make_float2(o2, o3);
                if (STATS) { s1 += (double)c2 + (double)c3;
                             s2 += (double)c2 * c2 + (double)c3 * c3; }
            }
        }
    }

    if (STATS) {
        sred[tid] = s1; __syncthreads();
        for (int o = 128; o > 0; o >>= 1) { if (tid < o) sred[tid] += sred[tid + o]; __syncthreads(); }
        if (tid == 0) atomicAdd(&sums[0], sred[0]);
        __syncthreads();
        sred[tid] = s2; __syncthreads();
        for (int o = 128; o > 0; o >>= 1) { if (tid < o) sred[tid] += sred[tid + o]; __syncthreads(); }
        if (tid == 0) atomicAdd(&sums[1], sred[0]);
    }
}

// ---------------- conv2 combine (float4): y2 = agg/deg + bl2 + r2, stats ----------------
__global__ void k_y2(const float* __restrict__ agg, const float* __restrict__ pr,
                     const float* __restrict__ bl2, const float* __restrict__ deg,
                     float* __restrict__ y2)
{
    __shared__ double sred[256];
    double s1 = 0.0, s2 = 0.0;
    const int n4 = N_NODES * 32;    // float4 elements
    for (int idx = blockIdx.x * blockDim.x + threadIdx.x; idx < n4; idx += gridDim.x * blockDim.x) {
        int i = idx >> 5, c = (idx & 31) * 4;
        float inv = 1.0f / fmaxf(deg[i], 1.0f);
        float4 a = *reinterpret_cast<const float4*>(agg + (size_t)i * 128 + c);
        float4 r = *reinterpret_cast<const float4*>(pr + (size_t)i * 256 + 128 + c);
        float4 b = *reinterpret_cast<const float4*>(bl2 + c);
        float4 y;
        y.x = a.x * inv + b.x + r.x;
        y.y = a.y * inv + b.y + r.y;
        y.z = a.z * inv + b.z + r.z;
        y.w = a.w * inv + b.w + r.w;
        *reinterpret_cast<float4*>(y2 + (size_t)i * 128 + c) = y;
        s1 += (double)y.x + (double)y.y + (double)y.z + (double)y.w;
        s2 += (double)y.x * y.x + (double)y.y * y.y + (double)y.z * y.z + (double)y.w * y.w;
    }
    int tid = threadIdx.x;
    sred[tid] = s1; __syncthreads();
    for (int o = 128; o > 0; o >>= 1) { if (tid < o) sred[tid] += sred[tid + o]; __syncthreads(); }
    if (tid == 0) atomicAdd(&g_sums[2], sred[0]);
    __syncthreads();
    sred[tid] = s2; __syncthreads();
    for (int o = 128; o > 0; o >>= 1) { if (tid < o) sred[tid] += sred[tid + o]; __syncthreads(); }
    if (tid == 0) atomicAdd(&g_sums[3], sred[0]);
}

// ---------------- launch ----------------
extern "C" void kernel_launch(void* const* d_in, const int* in_sizes, int n_in,
                              void* d_out, int out_size)
{
    const float* x    = (const float*)d_in[0];
    const void*  ei   =               d_in[1];
    const float* Wl1  = (const float*)d_in[2];
    const float* bl1  = (const float*)d_in[3];
    const float* Wr1  = (const float*)d_in[4];
    const float* ln1w = (const float*)d_in[5];
    const float* ln1b = (const float*)d_in[6];
    const float* W1   = (const float*)d_in[7];
    const float* b1   = (const float*)d_in[8];
    const float* W2   = (const float*)d_in[9];
    const float* b2   = (const float*)d_in[10];
    const float* Wl2  = (const float*)d_in[11];
    const float* bl2  = (const float*)d_in[12];
    const float* Wr2  = (const float*)d_in[13];
    const float* ln2w = (const float*)d_in[14];
    const float* ln2b = (const float*)d_in[15];
    const float* W3   = (const float*)d_in[16];
    const float* b3   = (const float*)d_in[17];
    const float* W4   = (const float*)d_in[18];
    const float* b4   = (const float*)d_in[19];
    float* out = (float*)d_out;

    float *agg, *deg, *y1, *pr, *y2;
    unsigned *a1, *z1, *t1, *h2, *z2, *t3, *bt1, *w1t, *w2t, *blr2, *w3t, *w4t;
    double* sums;
    cudaGetSymbolAddress((void**)&agg,  g_agg);
    cudaGetSymbolAddress((void**)&deg,  g_deg);
    cudaGetSymbolAddress((void**)&a1,   g_a1);
    cudaGetSymbolAddress((void**)&y1,   g_y1);
    cudaGetSymbolAddress((void**)&z1,   g_z1);
    cudaGetSymbolAddress((void**)&t1,   g_t1);
    cudaGetSymbolAddress((void**)&h2,   g_h2);
    cudaGetSymbolAddress((void**)&pr,   g_pr);
    cudaGetSymbolAddress((void**)&y2,   g_y2);
    cudaGetSymbolAddress((void**)&z2,   g_z2);
    cudaGetSymbolAddress((void**)&t3,   g_t3);
    cudaGetSymbolAddress((void**)&bt1,  g_bt1);
    cudaGetSymbolAddress((void**)&w1t,  g_w1t);
    cudaGetSymbolAddress((void**)&w2t,  g_w2t);
    cudaGetSymbolAddress((void**)&blr2, g_blr2);
    cudaGetSymbolAddress((void**)&w3t,  g_w3t);
    cudaGetSymbolAddress((void**)&w4t,  g_w4t);
    cudaGetSymbolAddress((void**)&sums, g_sums);

    cudaFuncSetAttribute(k_gemm<false, true,  true,  false>, cudaFuncAttributeMaxDynamicSharedMemorySize, GEMM_SMEM_BYTES);
    cudaFuncSetAttribute(k_gemm<true,  true,  false, true >, cudaFuncAttributeMaxDynamicSharedMemorySize, GEMM_SMEM_BYTES);
    cudaFuncSetAttribute(k_gemm<false, false, false, false>, cudaFuncAttributeMaxDynamicSharedMemorySize, GEMM_SMEM_BYTES);
    cudaFuncSetAttribute(k_gemm<false, true,  false, false>, cudaFuncAttributeMaxDynamicSharedMemorySize, GEMM_SMEM_BYTES);

    const int M = N_NODES;
    const unsigned gy = (M + 127) / 128;
    const int scatterBlocks = (N_EDGES * 32 + 255) / 256;

    // --- prep: all weights in one launch; init + zero agg/deg in one launch ---
    k_wtall<<<(WTALL_TOTAL + 255) / 256, 256>>>(Wl1, Wr1, W1, W2, Wl2, Wr2, W3, W4,
                                                bt1, w1t, w2t, blr2, w3t, w4t);
    k_start<<<(AGG4 + DEG4 + 255) / 256, 256>>>((const unsigned long long*)ei,
                                                (float4*)agg, (float4*)deg);

    // --- conv1 ---
    k_scatter<<<scatterBlocks, 256>>>(ei, x, 128, agg, deg, 1);
    k_prep1<<<(N_NODES * 32 + 255) / 256, 256>>>(agg, x, deg, a1);
    k_gemm<false, true, true, false><<<dim3(2, gy), 256, GEMM_SMEM_BYTES>>>(
        a1, bt1, bl1, y1, M, 256, 256, sums);
    k_lnrelu<<<(N_NODES * 64 + 255) / 256, 256>>>(y1, z1, ln1w, ln1b, 255, 0,
                                                  (double)N_NODES * 256.0, N_NODES * 64);
    k_gemm<true, true, false, true><<<dim3(4, gy), 256, GEMM_SMEM_BYTES>>>(
        z1, w1t, b1, (float*)t1, M, 512, 256, nullptr);
    k_gemm<true, true, false, true><<<dim3(2, gy), 256, GEMM_SMEM_BYTES>>>(
        t1, w2t, b2, (float*)h2, M, 256, 512, nullptr);

    // --- conv2 (projected-first): pr = h2 @ [Wl2 | Wr2] ---
    k_gemm<false, false, false, false><<<dim3(2, gy), 256, GEMM_SMEM_BYTES>>>(
        h2, blr2, nullptr, pr, M, 256, 256, nullptr);
    k_zerof4<<<(AGG4 + 255) / 256, 256>>>((float4*)agg);
    k_scatter<<<scatterBlocks, 256>>>(ei, pr, 256, agg, deg, 0);
    k_y2<<<1024, 256>>>(agg, pr, bl2, deg, y2);
    k_lnrelu<<<(N_NODES * 32 + 255) / 256, 256>>>(y2, z2, ln2w, ln2b, 127, 2,
                                                  (double)N_NODES * 128.0, N_NODES * 32);
    k_gemm<true, true, false, true><<<dim3(2, gy), 256, GEMM_SMEM_BYTES>>>(
        z2, w3t, b3, (float*)t3, M, 256, 128, nullptr);
    k_gemm<false, true, false, false><<<dim3(1, gy), 256, GEMM_SMEM_BYTES>>>(
        t3, w4t, b4, out, M, 128, 256, nullptr);
}

// round 10
// speedup vs baseline: 1.6237x; 1.2503x over previous
#include <cuda_runtime.h>
#include <cuda_fp16.h>

#define N_NODES 50000
#define N_EDGES 800000

// ---------------- scratch (static device globals; no allocation) ----------------
static __device__ float  g_agg[(size_t)N_NODES * 128];
static __device__ float  g_deg[N_NODES];
static __device__ __half g_a1 [(size_t)N_NODES * 256];   // fp16: [agg/deg | x]
static __device__ float  g_y1 [(size_t)N_NODES * 256];
static __device__ __half g_z1 [(size_t)N_NODES * 256];   // fp16 relu(LN1(y1))
static __device__ __half g_t1 [(size_t)N_NODES * 512];   // fp16
static __device__ __half g_h2 [(size_t)N_NODES * 256];   // fp16
static __device__ float  g_pr [(size_t)N_NODES * 256];   // [p | r2] fp32
static __device__ float  g_y2 [(size_t)N_NODES * 128];
static __device__ __half g_z2 [(size_t)N_NODES * 128];   // fp16 relu(LN2(y2))
static __device__ __half g_t3 [(size_t)N_NODES * 256];   // fp16
// transposed fp16 weights [n][k]
static __device__ __half g_bt1 [256 * 256];
static __device__ __half g_w1t [512 * 256];
static __device__ __half g_w2t [256 * 512];
static __device__ __half g_blr2[256 * 256];
static __device__ __half g_w3t [256 * 128];
static __device__ __half g_w4t [128 * 256];
static __device__ double g_sums[4];
static __device__ int    g_is64;

// ---------------- start: is64 detect + sums reset + zero agg & deg (float4) ----------------
#define AGG4 (N_NODES * 128 / 4)
#define DEG4 (N_NODES / 4)
__global__ void k_start(const unsigned long long* __restrict__ ei,
                        float4* __restrict__ agg4, float4* __restrict__ deg4)
{
    int idx = blockIdx.x * blockDim.x + threadIdx.x;
    if (idx == 0) {
        int ok = 1;
#pragma unroll
        for (int i = 0; i < 16; i++)
            ok &= ((ei[i] >> 32) == 0ull) ? 1 : 0;
        g_is64 = ok;
        g_sums[0] = 0.0; g_sums[1] = 0.0; g_sums[2] = 0.0; g_sums[3] = 0.0;
    }
    float4 z = make_float4(0.f, 0.f, 0.f, 0.f);
    if (idx < AGG4) agg4[idx] = z;
    else if (idx < AGG4 + DEG4) deg4[idx - AGG4] = z;
}

__global__ void k_zerof4(float4* __restrict__ p)
{
    int i = blockIdx.x * blockDim.x + threadIdx.x;
    if (i < AGG4) p[i] = make_float4(0.f, 0.f, 0.f, 0.f);
}

// ---------------- ALL weight transposes + fp16 convert in ONE kernel ----------------
__global__ void k_wtall(const float* __restrict__ Wl1, const float* __restrict__ Wr1,
                        const float* __restrict__ W1,  const float* __restrict__ W2,
                        const float* __restrict__ Wl2, const float* __restrict__ Wr2,
                        const float* __restrict__ W3,  const float* __restrict__ W4,
                        __half* __restrict__ bt1, __half* __restrict__ w1t,
                        __half* __restrict__ w2t, __half* __restrict__ blr2,
                        __half* __restrict__ w3t, __half* __restrict__ w4t)
{
    int i = blockIdx.x * blockDim.x + threadIdx.x;
    if (i < 32768)  { int k = i / 256, n = i % 256; bt1[n * 256 + k] = __float2half_rn(Wl1[i]); return; }
    i -= 32768;
    if (i < 32768)  { int k = i / 256, n = i % 256; bt1[n * 256 + k + 128] = __float2half_rn(Wr1[i]); return; }
    i -= 32768;
    if (i < 131072) { int k = i / 512, n = i % 512; w1t[n * 256 + k] = __float2half_rn(W1[i]); return; }
    i -= 131072;
    if (i < 131072) { int k = i / 256, n = i % 256; w2t[n * 512 + k] = __float2half_rn(W2[i]); return; }
    i -= 131072;
    if (i < 32768)  { int k = i / 128, n = i % 128; blr2[n * 256 + k] = __float2half_rn(Wl2[i]); return; }
    i -= 32768;
    if (i < 32768)  { int k = i / 128, n = i % 128; blr2[(n + 128) * 256 + k] = __float2half_rn(Wr2[i]); return; }
    i -= 32768;
    if (i < 32768)  { int k = i / 256, n = i % 256; w3t[n * 128 + k] = __float2half_rn(W3[i]); return; }
    i -= 32768;
    if (i < 32768)  { int k = i / 128, n = i % 128; w4t[n * 256 + k] = __float2half_rn(W4[i]); }
}
#define WTALL_TOTAL (32768 * 6 + 131072 * 2)

// ---------------- edge scatter: warp per edge, float4 vector-RED per lane ----------------
__global__ void k_scatter(const void* __restrict__ ei, const float* __restrict__ feat,
                          int fstride, float* __restrict__ agg, float* __restrict__ deg,
                          int addDeg)
{
    int gw   = (blockIdx.x * blockDim.x + threadIdx.x) >> 5;
    int lane = threadIdx.x & 31;
    if (gw >= N_EDGES) return;

    long long s, d;
    if (g_is64) {
        const long long* p = (const long long*)ei;
        s = p[gw]; d = p[N_EDGES + gw];
    } else {
        const int* p = (const int*)ei;
        s = p[gw];  d = p[N_EDGES + gw];
    }

    float4 v = *reinterpret_cast<const float4*>(feat + (size_t)s * fstride + lane * 4);
    float* dp = agg + (size_t)d * 128 + lane * 4;
    asm volatile("red.global.add.v4.f32 [%0], {%1,%2,%3,%4};"
                 :: "l"(dp), "f"(v.x), "f"(v.y), "f"(v.z), "f"(v.w) : "memory");
    if (addDeg && lane == 0) atomicAdd(deg + d, 1.0f);
}

// ---------------- conv1 A prep: A1 = fp16([agg/deg | x]) ----------------
__global__ void k_prep1(const float* __restrict__ agg, const float* __restrict__ x,
                        const float* __restrict__ deg, __half* __restrict__ A1)
{
    int idx = blockIdx.x * blockDim.x + threadIdx.x;
    if (idx >= N_NODES * 32) return;
    int i = idx >> 5, c = (idx & 31) * 4;
    float inv = 1.0f / fmaxf(deg[i], 1.0f);
    float4 a = *reinterpret_cast<const float4*>(agg + (size_t)i * 128 + c);
    float4 xv = *reinterpret_cast<const float4*>(x + (size_t)i * 128 + c);
    __half2 a01 = __floats2half2_rn(a.x * inv, a.y * inv);
    __half2 a23 = __floats2half2_rn(a.z * inv, a.w * inv);
    __half2 x01 = __floats2half2_rn(xv.x, xv.y);
    __half2 x23 = __floats2half2_rn(xv.z, xv.w);
    *reinterpret_cast<__half2*>(A1 + (size_t)i * 256 + c)       = a01;
    *reinterpret_cast<__half2*>(A1 + (size_t)i * 256 + c + 2)   = a23;
    *reinterpret_cast<__half2*>(A1 + (size_t)i * 256 + 128 + c)     = x01;
    *reinterpret_cast<__half2*>(A1 + (size_t)i * 256 + 128 + c + 2) = x23;
}

// ---------------- LN+ReLU -> fp16 (stats computed in-block from g_sums) ----------------
__global__ void k_lnrelu(const float* __restrict__ src, __half* __restrict__ dst,
                         const float* __restrict__ w, const float* __restrict__ b,
                         int Cmask, int statOff, double cnt, int total4)
{
    __shared__ float s_mu, s_rs;
    if (threadIdx.x == 0) {
        double mu  = g_sums[statOff] / cnt;
        double var = g_sums[statOff + 1] / cnt - mu * mu;
        s_mu = (float)mu;
        s_rs = (float)(1.0 / sqrt(var + 1e-5));
    }
    __syncthreads();
    int idx = blockIdx.x * blockDim.x + threadIdx.x;
    if (idx >= total4) return;
    float mu = s_mu, rs = s_rs;
    int c = (idx * 4) & Cmask;
    float4 v = reinterpret_cast<const float4*>(src)[idx];
    float4 w4 = *reinterpret_cast<const float4*>(w + c);
    float4 b4 = *reinterpret_cast<const float4*>(b + c);
    __half2 o01 = __floats2half2_rn(fmaxf((v.x - mu) * rs * w4.x + b4.x, 0.f),
                                    fmaxf((v.y - mu) * rs * w4.y + b4.y, 0.f));
    __half2 o23 = __floats2half2_rn(fmaxf((v.z - mu) * rs * w4.z + b4.z, 0.f),
                                    fmaxf((v.w - mu) * rs * w4.w + b4.w, 0.f));
    *reinterpret_cast<__half2*>(dst + (size_t)idx * 4)     = o01;
    *reinterpret_cast<__half2*>(dst + (size_t)idx * 4 + 2) = o23;
}

// ---------------- FP16 tensor-core GEMM, 3-stage cp.async ring, XOR swizzle ----------------
// smem row = 64 fp16 (128B) = 8 chunks of 16B; chunk ^= (row & 7). Tile K=64.
#define TILE_BYTES (128 * 128)
#define STAGE_BYTES (2 * TILE_BYTES)
#define NSTAGE 3
#define GEMM_SMEM_BYTES (NSTAGE * STAGE_BYTES)   // 98304

__device__ __forceinline__ void ldsm4(unsigned* r, unsigned addr)
{
    asm volatile("ldmatrix.sync.aligned.m8n8.x4.shared.b16 {%0,%1,%2,%3}, [%4];"
                 : "=r"(r[0]), "=r"(r[1]), "=r"(r[2]), "=r"(r[3]) : "r"(addr));
}

__device__ __forceinline__ void mma_f16(float* c, const unsigned* a,
                                        unsigned b0, unsigned b1)
{
    asm volatile(
        "mma.sync.aligned.m16n8k16.row.col.f32.f16.f16.f32 "
        "{%0,%1,%2,%3}, {%4,%5,%6,%7}, {%8,%9}, {%0,%1,%2,%3};\n"
        : "+f"(c[0]), "+f"(c[1]), "+f"(c[2]), "+f"(c[3])
        : "r"(a[0]), "r"(a[1]), "r"(a[2]), "r"(a[3]), "r"(b0), "r"(b1));
}

template <bool RELU, bool BIAS, bool STATS, bool HOUT>
__global__ void __launch_bounds__(256, 2)
k_gemm(const __half* __restrict__ A, const __half* __restrict__ Bt,
       const float* __restrict__ bias, float* __restrict__ C,
       int M, int Nc, int K, double* __restrict__ sums)
{
    extern __shared__ __align__(16) unsigned char dsm[];
    __shared__ double sred[256];

    const int tid  = threadIdx.x;
    const int lane = tid & 31;
    const int wid  = tid >> 5;
    const int g    = lane >> 2;
    const int t4   = lane & 3;
    const int warpM = (wid >> 2) * 64;
    const int warpN = (wid & 3) * 32;
    const int rowBase = blockIdx.y * 128;
    const int colBase = blockIdx.x * 128;

    float acc[4][4][4];
#pragma unroll
    for (int i = 0; i < 4; i++)
#pragma unroll
        for (int j = 0; j < 4; j++)
#pragma unroll
            for (int k = 0; k < 4; k++) acc[i][j][k] = 0.f;

    // ---- fill mapping: 2 threads per row, 4 chunks (16B = 8 fp16) each, XOR swizzle ----
    const int fR  = tid >> 1;
    const int fXr = fR & 7;
    const int fC0 = (tid & 1) * 4;
    const unsigned smBase = (unsigned)__cvta_generic_to_shared(dsm);
    const unsigned aRowDst = smBase + (unsigned)(fR * 128);
    const unsigned bRowDst = smBase + (unsigned)(TILE_BYTES + fR * 128);
    const bool aOk = (rowBase + fR) < M;
    const int  aSz = aOk ? 16 : 0;
    const __half* aSrcRow = A + (size_t)(aOk ? rowBase + fR : 0) * K + fC0 * 8;
    const __half* bSrcRow = Bt + (size_t)(colBase + fR) * K + fC0 * 8;

    // ---- ldmatrix lane mapping (XOR swizzle) ----
    const int aRowL = warpM + (lane & 7) + ((lane >> 3) & 1) * 8;
    const unsigned aRow0 = smBase + (unsigned)(aRowL * 128);
    const int xrA = lane & 7;
    const int cA  = (lane >> 4) & 1;
    const int bRowL = warpN + (lane & 7);
    const unsigned bRow0 = smBase + (unsigned)(TILE_BYTES + bRowL * 128);
    const int xrB = lane & 7;
    const int cB  = lane >> 3;

    auto FILL = [&](int s, int k0) {
        unsigned off = (unsigned)(s * STAGE_BYTES);
        const __half* as = aSrcRow + k0;
        const __half* bs = bSrcRow + k0;
#pragma unroll
        for (int j = 0; j < 4; j++) {
            unsigned dA = aRowDst + off + (unsigned)((((fC0 + j) ^ fXr)) << 4);
            asm volatile("cp.async.cg.shared.global [%0], [%1], 16, %2;"
                         :: "r"(dA), "l"(as + j * 8), "r"(aSz) : "memory");
        }
#pragma unroll
        for (int j = 0; j < 4; j++) {
            unsigned dB = bRowDst + off + (unsigned)((((fC0 + j) ^ fXr)) << 4);
            asm volatile("cp.async.cg.shared.global [%0], [%1], 16;"
                         :: "r"(dB), "l"(bs + j * 8) : "memory");
        }
        asm volatile("cp.async.commit_group;" ::: "memory");
    };

    auto MMA = [&](int s) {
        unsigned off = (unsigned)(s * STAGE_BYTES);
#pragma unroll
        for (int kbp = 0; kbp < 2; kbp++) {
            unsigned bf[4][4];
#pragma unroll
            for (int nt = 0; nt < 4; nt++)
                ldsm4(bf[nt], bRow0 + off + (unsigned)(nt * 8 * 128)
                              + (unsigned)(((cB + 4 * kbp) ^ xrB) << 4));
#pragma unroll
            for (int kk = 0; kk < 2; kk++) {
                int kb = kbp * 2 + kk;
                unsigned af[4][4];
#pragma unroll
                for (int mt = 0; mt < 4; mt++)
                    ldsm4(af[mt], aRow0 + off + (unsigned)(mt * 16 * 128)
                                  + (unsigned)(((cA + 2 * kb) ^ xrA) << 4));
#pragma unroll
                for (int nt = 0; nt < 4; nt++)
#pragma unroll
                    for (int mt = 0; mt < 4; mt++)
                        mma_f16(acc[mt][nt], af[mt], bf[nt][kk * 2], bf[nt][kk * 2 + 1]);
            }
        }
    };

    // -------- 3-stage pipelined mainloop, one sync per iter --------
    const int T = K >> 6;
    FILL(0, 0);
    if (T > 1) FILL(1, 64);
    int curS = 0;
    int fillS = (T > 1) ? 2 : 1;
    if (fillS >= NSTAGE) fillS -= NSTAGE;
    for (int i = 0; i < T; i++) {
        if (i + 1 < T) { asm volatile("cp.async.wait_group 1;" ::: "memory"); }
        else           { asm volatile("cp.async.wait_group 0;" ::: "memory"); }
        __syncthreads();
        if (i + 2 < T) {
            FILL(fillS, (i + 2) * 64);
            if (++fillS == NSTAGE) fillS = 0;
        }
        MMA(curS);
        if (++curS == NSTAGE) curS = 0;
    }

    // ---- epilogue ----
    __half* Ch = reinterpret_cast<__half*>(C);
    double s1 = 0.0, s2 = 0.0;
#pragma unroll
    for (int nt = 0; nt < 4; nt++) {
        int col = colBase + warpN + nt * 8 + 2 * t4;
        float2 bv = make_float2(0.f, 0.f);
        if (BIAS) bv = *reinterpret_cast<const float2*>(bias + col);
#pragma unroll
        for (int mt = 0; mt < 4; mt++) {
            int r0 = rowBase + warpM + mt * 16 + g;
            float c0 = acc[mt][nt][0] + bv.x;
            float c1 = acc[mt][nt][1] + bv.y;
            float c2 = acc[mt][nt][2] + bv.x;
            float c3 = acc[mt][nt][3] + bv.y;
            if (RELU) {
                c0 = fmaxf(c0, 0.f); c1 = fmaxf(c1, 0.f);
                c2 = fmaxf(c2, 0.f); c3 = fmaxf(c3, 0.f);
            }
            if (r0 < M) {
                if (HOUT)
                    *reinterpret_cast<__half2*>(Ch + (size_t)r0 * Nc + col) = __floats2half2_rn(c0, c1);
                else
                    *reinterpret_cast<float2*>(C + (size_t)r0 * Nc + col) = make_float2(c0, c1);
                if (STATS) { s1 += (double)c0 + (double)c1;
                             s2 += (double)c0 * c0 + (double)c1 * c1; }
            }
            if (r0 + 8 < M) {
                if (HOUT)
                    *reinterpret_cast<__half2*>(Ch + (size_t)(r0 + 8) * Nc + col) = __floats2half2_rn(c2, c3);
                else
                    *reinterpret_cast<float2*>(C + (size_t)(r0 + 8) * Nc + col) = make_float2(c2, c3);
                if (STATS) { s1 += (double)c2 + (double)c3;
                             s2 += (double)c2 * c2 + (double)c3 * c3; }
            }
        }
    }

    if (STATS) {
        sred[tid] = s1; __syncthreads();
        for (int o = 128; o > 0; o >>= 1) { if (tid < o) sred[tid] += sred[tid + o]; __syncthreads(); }
        if (tid == 0) atomicAdd(&sums[0], sred[0]);
        __syncthreads();
        sred[tid] = s2; __syncthreads();
        for (int o = 128; o > 0; o >>= 1) { if (tid < o) sred[tid] += sred[tid + o]; __syncthreads(); }
        if (tid == 0) atomicAdd(&sums[1], sred[0]);
    }
}

// ---------------- conv2 combine (float4): y2 = agg/deg + bl2 + r2, stats ----------------
__global__ void k_y2(const float* __restrict__ agg, const float* __restrict__ pr,
                     const float* __restrict__ bl2, const float* __restrict__ deg,
                     float* __restrict__ y2)
{
    __shared__ double sred[256];
    double s1 = 0.0, s2 = 0.0;
    const int n4 = N_NODES * 32;
    for (int idx = blockIdx.x * blockDim.x + threadIdx.x; idx < n4; idx += gridDim.x * blockDim.x) {
        int i = idx >> 5, c = (idx & 31) * 4;
        float inv = 1.0f / fmaxf(deg[i], 1.0f);
        float4 a = *reinterpret_cast<const float4*>(agg + (size_t)i * 128 + c);
        float4 r = *reinterpret_cast<const float4*>(pr + (size_t)i * 256 + 128 + c);
        float4 b = *reinterpret_cast<const float4*>(bl2 + c);
        float4 y;
        y.x = a.x * inv + b.x + r.x;
        y.y = a.y * inv + b.y + r.y;
        y.z = a.z * inv + b.z + r.z;
        y.w = a.w * inv + b.w + r.w;
        *reinterpret_cast<float4*>(y2 + (size_t)i * 128 + c) = y;
        s1 += (double)y.x + (double)y.y + (double)y.z + (double)y.w;
        s2 += (double)y.x * y.x + (double)y.y * y.y + (double)y.z * y.z + (double)y.w * y.w;
    }
    int tid = threadIdx.x;
    sred[tid] = s1; __syncthreads();
    for (int o = 128; o > 0; o >>= 1) { if (tid < o) sred[tid] += sred[tid + o]; __syncthreads(); }
    if (tid == 0) atomicAdd(&g_sums[2], sred[0]);
    __syncthreads();
    sred[tid] = s2; __syncthreads();
    for (int o = 128; o > 0; o >>= 1) { if (tid < o) sred[tid] += sred[tid + o]; __syncthreads(); }
    if (tid == 0) atomicAdd(&g_sums[3], sred[0]);
}

// ---------------- launch ----------------
extern "C" void kernel_launch(void* const* d_in, const int* in_sizes, int n_in,
                              void* d_out, int out_size)
{
    const float* x    = (const float*)d_in[0];
    const void*  ei   =               d_in[1];
    const float* Wl1  = (const float*)d_in[2];
    const float* bl1  = (const float*)d_in[3];
    const float* Wr1  = (const float*)d_in[4];
    const float* ln1w = (const float*)d_in[5];
    const float* ln1b = (const float*)d_in[6];
    const float* W1   = (const float*)d_in[7];
    const float* b1   = (const float*)d_in[8];
    const float* W2   = (const float*)d_in[9];
    const float* b2   = (const float*)d_in[10];
    const float* Wl2  = (const float*)d_in[11];
    const float* bl2  = (const float*)d_in[12];
    const float* Wr2  = (const float*)d_in[13];
    const float* ln2w = (const float*)d_in[14];
    const float* ln2b = (const float*)d_in[15];
    const float* W3   = (const float*)d_in[16];
    const float* b3   = (const float*)d_in[17];
    const float* W4   = (const float*)d_in[18];
    const float* b4   = (const float*)d_in[19];
    float* out = (float*)d_out;

    float *agg, *deg, *y1, *pr, *y2;
    __half *a1, *z1, *t1, *h2, *z2, *t3, *bt1, *w1t, *w2t, *blr2, *w3t, *w4t;
    double* sums;
    cudaGetSymbolAddress((void**)&agg,  g_agg);
    cudaGetSymbolAddress((void**)&deg,  g_deg);
    cudaGetSymbolAddress((void**)&a1,   g_a1);
    cudaGetSymbolAddress((void**)&y1,   g_y1);
    cudaGetSymbolAddress((void**)&z1,   g_z1);
    cudaGetSymbolAddress((void**)&t1,   g_t1);
    cudaGetSymbolAddress((void**)&h2,   g_h2);
    cudaGetSymbolAddress((void**)&pr,   g_pr);
    cudaGetSymbolAddress((void**)&y2,   g_y2);
    cudaGetSymbolAddress((void**)&z2,   g_z2);
    cudaGetSymbolAddress((void**)&t3,   g_t3);
    cudaGetSymbolAddress((void**)&bt1,  g_bt1);
    cudaGetSymbolAddress((void**)&w1t,  g_w1t);
    cudaGetSymbolAddress((void**)&w2t,  g_w2t);
    cudaGetSymbolAddress((void**)&blr2, g_blr2);
    cudaGetSymbolAddress((void**)&w3t,  g_w3t);
    cudaGetSymbolAddress((void**)&w4t,  g_w4t);
    cudaGetSymbolAddress((void**)&sums, g_sums);

    cudaFuncSetAttribute(k_gemm<false, true,  true,  false>, cudaFuncAttributeMaxDynamicSharedMemorySize, GEMM_SMEM_BYTES);
    cudaFuncSetAttribute(k_gemm<true,  true,  false, true >, cudaFuncAttributeMaxDynamicSharedMemorySize, GEMM_SMEM_BYTES);
    cudaFuncSetAttribute(k_gemm<false, false, false, false>, cudaFuncAttributeMaxDynamicSharedMemorySize, GEMM_SMEM_BYTES);
    cudaFuncSetAttribute(k_gemm<false, true,  false, false>, cudaFuncAttributeMaxDynamicSharedMemorySize, GEMM_SMEM_BYTES);

    const int M = N_NODES;
    const unsigned gy = (M + 127) / 128;
    const int scatterBlocks = (N_EDGES * 32 + 255) / 256;

    // --- prep ---
    k_wtall<<<(WTALL_TOTAL + 255) / 256, 256>>>(Wl1, Wr1, W1, W2, Wl2, Wr2, W3, W4,
                                                bt1, w1t, w2t, blr2, w3t, w4t);
    k_start<<<(AGG4 + DEG4 + 255) / 256, 256>>>((const unsigned long long*)ei,
                                                (float4*)agg, (float4*)deg);

    // --- conv1 ---
    k_scatter<<<scatterBlocks, 256>>>(ei, x, 128, agg, deg, 1);
    k_prep1<<<(N_NODES * 32 + 255) / 256, 256>>>(agg, x, deg, a1);
    k_gemm<false, true, true, false><<<dim3(2, gy), 256, GEMM_SMEM_BYTES>>>(
        a1, bt1, bl1, y1, M, 256, 256, sums);
    k_lnrelu<<<(N_NODES * 64 + 255) / 256, 256>>>(y1, z1, ln1w, ln1b, 255, 0,
                                                  (double)N_NODES * 256.0, N_NODES * 64);
    k_gemm<true, true, false, true><<<dim3(4, gy), 256, GEMM_SMEM_BYTES>>>(
        z1, w1t, b1, (float*)t1, M, 512, 256, nullptr);
    k_gemm<true, true, false, true><<<dim3(2, gy), 256, GEMM_SMEM_BYTES>>>(
        t1, w2t, b2, (float*)h2, M, 256, 512, nullptr);

    // --- conv2 (projected-first): pr = h2 @ [Wl2 | Wr2] ---
    k_gemm<false, false, false, false><<<dim3(2, gy), 256, GEMM_SMEM_BYTES>>>(
        h2, blr2, nullptr, pr, M, 256, 256, nullptr);
    k_zerof4<<<(AGG4 + 255) / 256, 256>>>((float4*)agg);
    k_scatter<<<scatterBlocks, 256>>>(ei, pr, 256, agg, deg, 0);
    k_y2<<<1024, 256>>>(agg, pr, bl2, deg, y2);
    k_lnrelu<<<(N_NODES * 32 + 255) / 256, 256>>>(y2, z2, ln2w, ln2b, 127, 2,
                                                  (double)N_NODES * 128.0, N_NODES * 32);
    k_gemm<true, true, false, true><<<dim3(2, gy), 256, GEMM_SMEM_BYTES>>>(
        z2, w3t, b3, (float*)t3, M, 256, 128, nullptr);
    k_gemm<false, true, false, false><<<dim3(1, gy), 256, GEMM_SMEM_BYTES>>>(
        t3, w4t, b4, out, M, 128, 256, nullptr);
}